// round 2
// baseline (speedup 1.0000x reference)
#include <cuda_runtime.h>
#include <math.h>

#define NB 64
#define TT 512
#define DD 1024
#define HH 1024
#define FOURH 4096

// Scratch (allocation-free rule: __device__ globals)
__device__ float g_xw[(size_t)NB * TT * FOURH];  // 512 MiB: precomputed x@Wx + b
__device__ float g_c[NB * HH];                   // LSTM cell state

// ---------------------------------------------------------------------------
// zero the cell state
// ---------------------------------------------------------------------------
__global__ void zero_c_kernel(float* __restrict__ c) {
    c[blockIdx.x * 1024 + threadIdx.x] = 0.0f;
}

// ---------------------------------------------------------------------------
// xW GEMM: C[M,N] = A[M,K] @ B[K,N] + bias ; M=32768, K=1024, N=4096
// 128x128 CTA tile, BK=8, 8x8 register tile, 256 threads.
// ---------------------------------------------------------------------------
__global__ __launch_bounds__(256, 2) void xw_gemm_kernel(
    const float* __restrict__ A, const float* __restrict__ B,
    const float* __restrict__ bias, float* __restrict__ C)
{
    const int M = NB * TT, N = FOURH, K = DD;
    __shared__ float As[8][128];
    __shared__ float Bs[8][128];

    const int tid = threadIdx.x;
    const int bx = blockIdx.x;   // N tile
    const int by = blockIdx.y;   // M tile

    const int arow = tid >> 1;            // 0..127
    const int acol = (tid & 1) << 2;      // 0 or 4
    const int brow = tid >> 5;            // 0..7
    const int bcol = (tid & 31) << 2;     // 0..124

    const float* Aptr = A + (size_t)(by * 128 + arow) * K + acol;
    const float* Bptr = B + (size_t)brow * N + bx * 128 + bcol;

    const int ty = (tid >> 4) << 3;       // 0..120
    const int tx = (tid & 15) << 3;       // 0..120

    float acc[8][8];
    #pragma unroll
    for (int i = 0; i < 8; i++)
        #pragma unroll
        for (int j = 0; j < 8; j++) acc[i][j] = 0.0f;

    float ra[8], rb[8];

    for (int k0 = 0; k0 < K; k0 += 8) {
        float4 av = *(const float4*)Aptr;  Aptr += 8;
        float4 bv = *(const float4*)Bptr;  Bptr += (size_t)8 * N;

        __syncthreads();
        As[acol + 0][arow] = av.x;
        As[acol + 1][arow] = av.y;
        As[acol + 2][arow] = av.z;
        As[acol + 3][arow] = av.w;
        *(float4*)&Bs[brow][bcol] = bv;
        __syncthreads();

        #pragma unroll
        for (int k = 0; k < 8; k++) {
            *(float4*)&ra[0] = *(const float4*)&As[k][ty];
            *(float4*)&ra[4] = *(const float4*)&As[k][ty + 4];
            *(float4*)&rb[0] = *(const float4*)&Bs[k][tx];
            *(float4*)&rb[4] = *(const float4*)&Bs[k][tx + 4];
            #pragma unroll
            for (int i = 0; i < 8; i++)
                #pragma unroll
                for (int j = 0; j < 8; j++)
                    acc[i][j] += ra[i] * rb[j];
        }
    }

    // epilogue: add bias, store
    float bv0[8];
    #pragma unroll
    for (int j = 0; j < 8; j++) bv0[j] = bias[bx * 128 + tx + j];

    #pragma unroll
    for (int i = 0; i < 8; i++) {
        float* crow = C + (size_t)(by * 128 + ty + i) * N + bx * 128 + tx;
        float4 v0, v1;
        v0.x = acc[i][0] + bv0[0]; v0.y = acc[i][1] + bv0[1];
        v0.z = acc[i][2] + bv0[2]; v0.w = acc[i][3] + bv0[3];
        v1.x = acc[i][4] + bv0[4]; v1.y = acc[i][5] + bv0[5];
        v1.z = acc[i][6] + bv0[6]; v1.w = acc[i][7] + bv0[7];
        *(float4*)&crow[0] = v0;
        *(float4*)&crow[4] = v1;
    }
}

// ---------------------------------------------------------------------------
// One LSTM timestep.
//   grid = (64 jh-blocks, 2 n-blocks), 256 threads.
//   Each CTA: n in [nb*32, nb*32+32), jh in [jb*16, jb*16+16).
//   Computes a[n][g*H + jh] = xw + h_{t-1} @ Wh for the 64 columns
//   {g*1024 + jb*16 + jj}, then gates + c/h update.
// ---------------------------------------------------------------------------
__global__ __launch_bounds__(256) void lstm_step_kernel(
    const float* __restrict__ hprev, int hstride,      // h_{t-1}[n*hstride + k]
    const float* __restrict__ Wh,                      // (1024, 4096)
    const float* __restrict__ xw,                      // g_xw + t*4096; n-stride TT*4096
    float* __restrict__ outp,                          // d_out + t*1024; n-stride TT*1024
    float* __restrict__ cst)                           // (64, 1024)
{
    __shared__ float whs[16][64];      // Wh tile: [kr][local col l = g*16+jj]
    __shared__ float hs[16][33];       // h tile transposed (padded)
    __shared__ float as_[32][80];      // preactivations (padded, stride 80)

    const int tid = threadIdx.x;
    const int jb = blockIdx.x;     // 0..63
    const int nb = blockIdx.y;     // 0..1

    const int lx = tid & 15;       // l-group: l = lx*4..lx*4+3
    const int ly = tid >> 4;       // n-group: n = ly*2, ly*2+1

    // Wh tile load mapping: 16 k-rows x 16 float4 chunks
    const int wkr = tid >> 4;                  // 0..15
    const int wch = tid & 15;                  // 0..15
    const int wg  = wch >> 2;                  // gate 0..3
    const int wq  = wch & 3;                   // float4 group within 16 cols
    const size_t wcol = (size_t)wg * 1024 + jb * 16 + wq * 4;

    // h tile load mapping: 32 n x 8 k-pairs
    const int hn = tid >> 3;                   // 0..31
    const int hk = (tid & 7) << 1;             // 0,2,...,14
    const float* hrow = hprev + (size_t)(nb * 32 + hn) * hstride;

    float acc[2][4] = {{0.f,0.f,0.f,0.f},{0.f,0.f,0.f,0.f}};

    for (int k0 = 0; k0 < HH; k0 += 16) {
        float4 wv = *(const float4*)(Wh + (size_t)(k0 + wkr) * FOURH + wcol);
        float2 hv = *(const float2*)(hrow + k0 + hk);

        __syncthreads();
        *(float4*)&whs[wkr][wch * 4] = wv;
        hs[hk][hn]     = hv.x;
        hs[hk + 1][hn] = hv.y;
        __syncthreads();

        #pragma unroll
        for (int kr = 0; kr < 16; kr++) {
            float hr0 = hs[kr][ly * 2];
            float hr1 = hs[kr][ly * 2 + 1];
            float4 w = *(const float4*)&whs[kr][lx * 4];
            acc[0][0] += hr0 * w.x; acc[0][1] += hr0 * w.y;
            acc[0][2] += hr0 * w.z; acc[0][3] += hr0 * w.w;
            acc[1][0] += hr1 * w.x; acc[1][1] += hr1 * w.y;
            acc[1][2] += hr1 * w.z; acc[1][3] += hr1 * w.w;
        }
    }

    __syncthreads();
    // add xw projection, stage preactivations in shared
    #pragma unroll
    for (int i = 0; i < 2; i++) {
        const int n = ly * 2 + i;
        const float* xwrow = xw + (size_t)(nb * 32 + n) * ((size_t)TT * FOURH);
        #pragma unroll
        for (int j = 0; j < 4; j++) {
            const int l = lx * 4 + j;
            const int col = (l >> 4) * 1024 + jb * 16 + (l & 15);
            as_[n][l] = acc[i][j] + xwrow[col];
        }
    }
    __syncthreads();

    // gates + state update: 512 (n,jj) pairs, 2 per thread
    #pragma unroll
    for (int i = 0; i < 2; i++) {
        const int p = tid + i * 256;
        const int n = p >> 4;          // 0..31
        const int jj = p & 15;         // 0..15

        const float ai = as_[n][jj];
        const float af = as_[n][16 + jj];
        const float ao = as_[n][32 + jj];
        const float ag = as_[n][48 + jj];

        const float ig = 1.0f / (1.0f + __expf(-ai));
        const float fg = 1.0f / (1.0f + __expf(-af));
        const float og = 1.0f / (1.0f + __expf(-ao));
        const float gg = 2.0f / (1.0f + __expf(-2.0f * ag)) - 1.0f;

        const size_t cidx = (size_t)(nb * 32 + n) * HH + jb * 16 + jj;
        const float cv = fg * cst[cidx] + ig * gg;
        cst[cidx] = cv;
        const float th = 2.0f / (1.0f + __expf(-2.0f * cv)) - 1.0f;
        outp[(size_t)(nb * 32 + n) * ((size_t)TT * HH) + jb * 16 + jj] = og * th;
    }
}

// ---------------------------------------------------------------------------
extern "C" void kernel_launch(void* const* d_in, const int* in_sizes, int n_in,
                              void* d_out, int out_size)
{
    const float* x  = (const float*)d_in[0];   // (64, 512, 1024)
    const float* h0 = (const float*)d_in[1];   // (64, 1024)
    const float* Wx = (const float*)d_in[2];   // (1024, 4096)
    const float* Wh = (const float*)d_in[3];   // (1024, 4096)
    const float* b  = (const float*)d_in[4];   // (4096,)
    float* out = (float*)d_out;                // (64, 512, 1024)

    float* xw = nullptr;
    float* cst = nullptr;
    cudaGetSymbolAddress((void**)&xw, g_xw);
    cudaGetSymbolAddress((void**)&cst, g_c);

    // 1. zero cell state
    zero_c_kernel<<<NB, 1024>>>(cst);

    // 2. precompute xW = x @ Wx + b  (fully parallel GEMM)
    {
        dim3 grid(FOURH / 128, (NB * TT) / 128);
        xw_gemm_kernel<<<grid, 256>>>(x, Wx, b, xw);
    }

    // 3. 512 sequential timesteps
    for (int t = 0; t < TT; t++) {
        const float* hprev = (t == 0) ? h0 : (out + (size_t)(t - 1) * HH);
        const int hstride  = (t == 0) ? HH : (TT * HH);
        lstm_step_kernel<<<dim3(64, 2), 256>>>(
            hprev, hstride, Wh,
            xw + (size_t)t * FOURH,
            out + (size_t)t * HH,
            cst);
    }
}

// round 4
// speedup vs baseline: 1.9292x; 1.9292x over previous
#include <cuda_runtime.h>
#include <cuda_bf16.h>
#include <math.h>
#include <stdint.h>

#define NB 64
#define TT 512
#define DD 1024
#define HH 1024
#define FOURH 4096

// ---------------------------------------------------------------------------
// Scratch (__device__ globals; allocation-free rule)
// ---------------------------------------------------------------------------
__device__ float          g_xw[(size_t)NB * TT * FOURH];      // 512 MiB xW+b (permuted cols)
__device__ float          g_c[NB * HH];                       // cell state [n][j]
__device__ __nv_bfloat16  g_xhi[(size_t)NB * TT * DD];        // 64 MiB
__device__ __nv_bfloat16  g_xlo[(size_t)NB * TT * DD];        // 64 MiB
__device__ __nv_bfloat16  g_wxt_hi[(size_t)FOURH * DD];       // WxT perm [j'][k]
__device__ __nv_bfloat16  g_wxt_lo[(size_t)FOURH * DD];
__device__ __nv_bfloat16  g_wht_hi[(size_t)FOURH * DD];       // WhT perm [j'][k]
__device__ __nv_bfloat16  g_wht_lo[(size_t)FOURH * DD];
__device__ __nv_bfloat16  g_h_hi[2][NB * HH];                 // h double buffer (bf16 hi)
__device__ __nv_bfloat16  g_h_lo[2][NB * HH];                 // h double buffer (bf16 lo)
__device__ float          g_biasp[FOURH];                     // permuted bias

// ---------------------------------------------------------------------------
// Helpers
// ---------------------------------------------------------------------------
__device__ __forceinline__ uint32_t smem_u32(const void* p) {
    uint32_t a;
    asm("{ .reg .u64 t; cvta.to.shared.u64 t, %1; cvt.u32.u64 %0, t; }"
        : "=r"(a) : "l"(p));
    return a;
}

#define CP16(dst, src) \
    asm volatile("cp.async.cg.shared.global [%0], [%1], 16;" :: "r"(dst), "l"(src) : "memory")
#define CP_COMMIT() asm volatile("cp.async.commit_group;" ::: "memory")
#define CP_WAIT(n)  asm volatile("cp.async.wait_group %0;" :: "n"(n) : "memory")

#define LDSM4(r0, r1, r2, r3, addr) \
    asm volatile("ldmatrix.sync.aligned.m8n8.x4.shared.b16 {%0,%1,%2,%3}, [%4];" \
                 : "=r"(r0), "=r"(r1), "=r"(r2), "=r"(r3) : "r"(addr))

#define MMA_BF16(c0, c1, c2, c3, a0, a1, a2, a3, b0, b1) \
    asm volatile("mma.sync.aligned.m16n8k16.row.col.f32.bf16.bf16.f32 " \
                 "{%0,%1,%2,%3}, {%4,%5,%6,%7}, {%8,%9}, {%0,%1,%2,%3};" \
                 : "+f"(c0), "+f"(c1), "+f"(c2), "+f"(c3) \
                 : "r"(a0), "r"(a1), "r"(a2), "r"(a3), "r"(b0), "r"(b1))

__device__ __forceinline__ float fsigmoid(float x) { return 1.0f / (1.0f + __expf(-x)); }
__device__ __forceinline__ float ftanh(float x)    { return 2.0f / (1.0f + __expf(-2.0f * x)) - 1.0f; }

// ---------------------------------------------------------------------------
// Prep kernels
// ---------------------------------------------------------------------------
__global__ void prep_small_kernel(const float* __restrict__ h0, const float* __restrict__ b) {
    int i = blockIdx.x * 1024 + threadIdx.x;
    if (i < NB * HH) {
        g_c[i] = 0.0f;
        float v = h0[i];
        __nv_bfloat16 hi = __float2bfloat16(v);
        g_h_hi[0][i] = hi;
        g_h_lo[0][i] = __float2bfloat16(v - __bfloat162float(hi));
    }
    if (i < FOURH) {
        int jp = (i & 1023) * 4 + (i >> 10);     // perm: col g*1024+jh -> jh*4+g
        g_biasp[jp] = b[i];
    }
}

__global__ void split_x_kernel(const float* __restrict__ x) {
    size_t i = ((size_t)blockIdx.x * 256 + threadIdx.x) * 4;
    float4 v = *(const float4*)(x + i);
    __nv_bfloat16 h0 = __float2bfloat16(v.x), h1 = __float2bfloat16(v.y);
    __nv_bfloat16 h2 = __float2bfloat16(v.z), h3 = __float2bfloat16(v.w);
    __nv_bfloat162* ph = (__nv_bfloat162*)(g_xhi + i);
    __nv_bfloat162* pl = (__nv_bfloat162*)(g_xlo + i);
    ph[0] = __nv_bfloat162(h0, h1);
    ph[1] = __nv_bfloat162(h2, h3);
    pl[0] = __nv_bfloat162(__float2bfloat16(v.x - __bfloat162float(h0)),
                           __float2bfloat16(v.y - __bfloat162float(h1)));
    pl[1] = __nv_bfloat162(__float2bfloat16(v.z - __bfloat162float(h2)),
                           __float2bfloat16(v.w - __bfloat162float(h3)));
}

// W (1024 x 4096, k-major rows) -> out[j'][k] bf16 hi/lo with gate permutation.
__global__ void transpose_split_kernel(const float* __restrict__ W,
                                       __nv_bfloat16* __restrict__ ohi,
                                       __nv_bfloat16* __restrict__ olo) {
    __shared__ float ts[32][33];
    const int k0 = blockIdx.x * 32;
    const int c0 = blockIdx.y * 32;
    const int tx = threadIdx.x, ty = threadIdx.y;  // 32 x 8
    #pragma unroll
    for (int i = 0; i < 4; i++)
        ts[ty + 8 * i][tx] = W[(size_t)(k0 + ty + 8 * i) * FOURH + c0 + tx];
    __syncthreads();
    #pragma unroll
    for (int i = 0; i < 4; i++) {
        int c = c0 + ty + 8 * i;
        int jp = (c & 1023) * 4 + (c >> 10);
        float v = ts[tx][ty + 8 * i];
        __nv_bfloat16 hi = __float2bfloat16(v);
        ohi[(size_t)jp * DD + k0 + tx] = hi;
        olo[(size_t)jp * DD + k0 + tx] = __float2bfloat16(v - __bfloat162float(hi));
    }
}

// ---------------------------------------------------------------------------
// xW GEMM via mma.sync: g_xw[token][j'] = x @ WxT_perm^T + bias_perm
// CTA tile 128(token) x 128(j'), k-chunk 64, 3-stage cp.async pipeline.
// grid (32 ntiles, 256 mtiles), 256 threads = 8 warps (2 m-warps x 4 n-warps),
// warp tile 64x32.
// ---------------------------------------------------------------------------
#define G_STAGE 65536   // Ah 16K | Al 16K | Bh 16K | Bl 16K
#define G_SMEM  (3 * G_STAGE)

__global__ __launch_bounds__(256, 1)
void xw_gemm_mma() {
    extern __shared__ char smem[];
    const uint32_t sb = smem_u32(smem);
    const int tid = threadIdx.x;
    const int nbase = blockIdx.x * 128;
    const int mbase = blockIdx.y * 128;

    const __nv_bfloat16* Ahg = g_xhi + (size_t)mbase * DD;
    const __nv_bfloat16* Alg = g_xlo + (size_t)mbase * DD;
    const __nv_bfloat16* Bhg = g_wxt_hi + (size_t)nbase * DD;
    const __nv_bfloat16* Blg = g_wxt_lo + (size_t)nbase * DD;

    // cp.async mapping: 128 rows x 8 x 16B per array, 4 per thread per array
    auto cp_chunk = [&](int c, int st) {
        const int k0 = c * 64;
        const uint32_t ah = sb + st * G_STAGE;
        #pragma unroll
        for (int i = 0; i < 4; i++) {
            int idx = tid + i * 256;
            int row = idx >> 3, ch = idx & 7;
            uint32_t o = (uint32_t)(row * 128) + (uint32_t)((ch * 16) ^ ((row & 7) * 16));
            CP16(ah + o,         (const char*)(Ahg + (size_t)row * DD + k0) + ch * 16);
            CP16(ah + 16384 + o, (const char*)(Alg + (size_t)row * DD + k0) + ch * 16);
            CP16(ah + 32768 + o, (const char*)(Bhg + (size_t)row * DD + k0) + ch * 16);
            CP16(ah + 49152 + o, (const char*)(Blg + (size_t)row * DD + k0) + ch * 16);
        }
        CP_COMMIT();
    };

    const int wid = tid >> 5, lane = tid & 31;
    const int wm = wid >> 2, wn = wid & 3;      // warp grid 2x4
    const int m0 = wm * 64, n0 = wn * 32;
    const int gid = lane >> 2, tig = lane & 3;

    // ldmatrix lane addressing (A: m16k16 .x4; B pair: n16k16 .x4)
    const int a_r = lane & 15;
    const uint32_t a_k = ((lane >> 4) & 1) * 16;
    const uint32_t a_x = (uint32_t)((a_r & 7) * 16);
    const int b_r = (lane & 7) + ((lane >> 4) & 1) * 8;
    const uint32_t b_k = ((lane >> 3) & 1) * 16;
    const uint32_t b_x = (uint32_t)((lane & 7) * 16);

    float acc[4][4][4];
    #pragma unroll
    for (int mt = 0; mt < 4; mt++)
        #pragma unroll
        for (int nt = 0; nt < 4; nt++)
            #pragma unroll
            for (int q = 0; q < 4; q++) acc[mt][nt][q] = 0.0f;

    cp_chunk(0, 0);
    cp_chunk(1, 1);

    for (int c = 0; c < 16; c++) {
        if (c + 2 < 16) { cp_chunk(c + 2, (c + 2) % 3); CP_WAIT(2); }
        else if (c + 1 < 16) { CP_WAIT(1); }
        else { CP_WAIT(0); }
        __syncthreads();

        const uint32_t base = sb + (c % 3) * G_STAGE;
        #pragma unroll
        for (int kk = 0; kk < 4; kk++) {
            const uint32_t ka = ((uint32_t)(kk * 32) + a_k) ^ a_x;
            const uint32_t kb = ((uint32_t)(kk * 32) + b_k) ^ b_x;
            uint32_t ah[4][4], al[4][4], bh[2][4], bl[2][4];
            #pragma unroll
            for (int mt = 0; mt < 4; mt++) {
                uint32_t ra = base + (uint32_t)((m0 + mt * 16 + a_r) * 128);
                LDSM4(ah[mt][0], ah[mt][1], ah[mt][2], ah[mt][3], ra + ka);
                LDSM4(al[mt][0], al[mt][1], al[mt][2], al[mt][3], ra + 16384 + ka);
            }
            #pragma unroll
            for (int p = 0; p < 2; p++) {
                uint32_t rb = base + 32768 + (uint32_t)((n0 + p * 16 + b_r) * 128);
                LDSM4(bh[p][0], bh[p][1], bh[p][2], bh[p][3], rb + kb);
                LDSM4(bl[p][0], bl[p][1], bl[p][2], bl[p][3], rb + 16384 + kb);
            }
            #pragma unroll
            for (int mt = 0; mt < 4; mt++)
                #pragma unroll
                for (int nt = 0; nt < 4; nt++) {
                    const int p = nt >> 1, hf = (nt & 1) * 2;
                    MMA_BF16(acc[mt][nt][0], acc[mt][nt][1], acc[mt][nt][2], acc[mt][nt][3],
                             ah[mt][0], ah[mt][1], ah[mt][2], ah[mt][3],
                             bh[p][hf], bh[p][hf + 1]);
                    MMA_BF16(acc[mt][nt][0], acc[mt][nt][1], acc[mt][nt][2], acc[mt][nt][3],
                             ah[mt][0], ah[mt][1], ah[mt][2], ah[mt][3],
                             bl[p][hf], bl[p][hf + 1]);
                    MMA_BF16(acc[mt][nt][0], acc[mt][nt][1], acc[mt][nt][2], acc[mt][nt][3],
                             al[mt][0], al[mt][1], al[mt][2], al[mt][3],
                             bh[p][hf], bh[p][hf + 1]);
                }
        }
        __syncthreads();
    }

    // epilogue: add permuted bias, store float2 pairs
    #pragma unroll
    for (int nt = 0; nt < 4; nt++) {
        const int col = nbase + n0 + nt * 8 + tig * 2;
        float2 bv = *(const float2*)&g_biasp[col];
        #pragma unroll
        for (int mt = 0; mt < 4; mt++) {
            const int row = mbase + m0 + mt * 16 + gid;
            float2 v0, v1;
            v0.x = acc[mt][nt][0] + bv.x; v0.y = acc[mt][nt][1] + bv.y;
            v1.x = acc[mt][nt][2] + bv.x; v1.y = acc[mt][nt][3] + bv.y;
            *(float2*)&g_xw[(size_t)row * FOURH + col] = v0;
            *(float2*)&g_xw[(size_t)(row + 8) * FOURH + col] = v1;
        }
    }
}

// ---------------------------------------------------------------------------
// LSTM step via mma.sync: D[j'l][n] = WhT_perm(slice) . h^T, then gates.
// grid 32 CTAs x 512 threads. CTA jb: j' in [jb*128, jb*128+128) (= 32 hidden
// units x 4 gates), all 64 batch rows. 16 warps (8 m-warps x 2 n-warps),
// warp tile m16 x n32. k-chunk 64, 3-stage pipeline.
// ---------------------------------------------------------------------------
#define S_STAGE 49152   // Ah 16K | Al 16K | Bh 8K | Bl 8K
#define S_SMEM  (3 * S_STAGE)

__global__ __launch_bounds__(512, 1)
void lstm_step_mma(int t, float* __restrict__ out) {
    extern __shared__ char smem[];
    const uint32_t sb = smem_u32(smem);
    const int tid = threadIdx.x;
    const int jb = blockIdx.x;     // 0..31

    const __nv_bfloat16* Ahg = g_wht_hi + (size_t)jb * 128 * DD;
    const __nv_bfloat16* Alg = g_wht_lo + (size_t)jb * 128 * DD;
    const __nv_bfloat16* Bhg = g_h_hi[t & 1];
    const __nv_bfloat16* Blg = g_h_lo[t & 1];

    auto cp_chunk = [&](int c, int st) {
        const int k0 = c * 64;
        const uint32_t ah = sb + st * S_STAGE;
        #pragma unroll
        for (int i = 0; i < 2; i++) {                 // A: 128 rows x 8
            int idx = tid + i * 512;
            int row = idx >> 3, ch = idx & 7;
            uint32_t o = (uint32_t)(row * 128) + (uint32_t)((ch * 16) ^ ((row & 7) * 16));
            CP16(ah + o,         (const char*)(Ahg + (size_t)row * DD + k0) + ch * 16);
            CP16(ah + 16384 + o, (const char*)(Alg + (size_t)row * DD + k0) + ch * 16);
        }
        {                                             // B: 64 rows x 8
            int row = tid >> 3, ch = tid & 7;
            uint32_t o = (uint32_t)(row * 128) + (uint32_t)((ch * 16) ^ ((row & 7) * 16));
            CP16(ah + 32768 + o, (const char*)(Bhg + (size_t)row * DD + k0) + ch * 16);
            CP16(ah + 40960 + o, (const char*)(Blg + (size_t)row * DD + k0) + ch * 16);
        }
        CP_COMMIT();
    };

    const int wid = tid >> 5, lane = tid & 31;
    const int wm = wid >> 1, wn = wid & 1;     // 8 x 2
    const int m0 = wm * 16, n0 = wn * 32;
    const int gid = lane >> 2, tig = lane & 3;

    const int a_r = lane & 15;
    const uint32_t a_k = ((lane >> 4) & 1) * 16;
    const uint32_t a_x = (uint32_t)((a_r & 7) * 16);
    const int b_r = (lane & 7) + ((lane >> 4) & 1) * 8;
    const uint32_t b_k = ((lane >> 3) & 1) * 16;
    const uint32_t b_x = (uint32_t)((lane & 7) * 16);

    float acc[4][4];
    #pragma unroll
    for (int nt = 0; nt < 4; nt++)
        #pragma unroll
        for (int q = 0; q < 4; q++) acc[nt][q] = 0.0f;

    cp_chunk(0, 0);
    cp_chunk(1, 1);

    for (int c = 0; c < 16; c++) {
        if (c + 2 < 16) { cp_chunk(c + 2, (c + 2) % 3); CP_WAIT(2); }
        else if (c + 1 < 16) { CP_WAIT(1); }
        else { CP_WAIT(0); }
        __syncthreads();

        const uint32_t base = sb + (c % 3) * S_STAGE;
        const uint32_t raw = base + (uint32_t)((m0 + a_r) * 128);
        #pragma unroll
        for (int kk = 0; kk < 4; kk++) {
            const uint32_t ka = ((uint32_t)(kk * 32) + a_k) ^ a_x;
            const uint32_t kb = ((uint32_t)(kk * 32) + b_k) ^ b_x;
            uint32_t ah[4], al[4], bh[2][4], bl[2][4];
            LDSM4(ah[0], ah[1], ah[2], ah[3], raw + ka);
            LDSM4(al[0], al[1], al[2], al[3], raw + 16384 + ka);
            #pragma unroll
            for (int p = 0; p < 2; p++) {
                uint32_t rb = base + 32768 + (uint32_t)((n0 + p * 16 + b_r) * 128);
                LDSM4(bh[p][0], bh[p][1], bh[p][2], bh[p][3], rb + kb);
                LDSM4(bl[p][0], bl[p][1], bl[p][2], bl[p][3], rb + 8192 + kb);
            }
            #pragma unroll
            for (int nt = 0; nt < 4; nt++) {
                const int p = nt >> 1, hf = (nt & 1) * 2;
                MMA_BF16(acc[nt][0], acc[nt][1], acc[nt][2], acc[nt][3],
                         ah[0], ah[1], ah[2], ah[3], bh[p][hf], bh[p][hf + 1]);
                MMA_BF16(acc[nt][0], acc[nt][1], acc[nt][2], acc[nt][3],
                         ah[0], ah[1], ah[2], ah[3], bl[p][hf], bl[p][hf + 1]);
                MMA_BF16(acc[nt][0], acc[nt][1], acc[nt][2], acc[nt][3],
                         al[0], al[1], al[2], al[3], bh[p][hf], bh[p][hf + 1]);
            }
        }
        __syncthreads();
    }

    // Stage preactivations to a_s[n][j'l], padded row stride 132 floats.
    float* a_s = (float*)smem;
    {
        const int j = m0 + gid;
        #pragma unroll
        for (int nt = 0; nt < 4; nt++) {
            const int n = n0 + nt * 8 + tig * 2;
            a_s[n * 132 + j]           = acc[nt][0];
            a_s[(n + 1) * 132 + j]     = acc[nt][1];
            a_s[n * 132 + j + 8]       = acc[nt][2];
            a_s[(n + 1) * 132 + j + 8] = acc[nt][3];
        }
    }
    __syncthreads();

    // Gates: warp w handles n = w*4 .. w*4+3; lane = hidden unit jhl (0..31).
    {
        const int jhl = lane;
        const int jg = jb * 32 + jhl;
        __nv_bfloat16* nhhi = g_h_hi[(t + 1) & 1];
        __nv_bfloat16* nhlo = g_h_lo[(t + 1) & 1];
        #pragma unroll
        for (int r = 0; r < 4; r++) {
            const int n = wid * 4 + r;
            float4 a4 = *(float4*)&a_s[n * 132 + jhl * 4];
            const float* xr = g_xw + ((size_t)n * TT + t) * FOURH + jb * 128 + jhl * 4;
            float4 x4 = *(const float4*)xr;
            float ig = fsigmoid(a4.x + x4.x);
            float fg = fsigmoid(a4.y + x4.y);
            float og = fsigmoid(a4.z + x4.z);
            float gg = ftanh(a4.w + x4.w);
            const int ci = n * HH + jg;
            float cn = fg * g_c[ci] + ig * gg;
            g_c[ci] = cn;
            float h = og * ftanh(cn);
            out[((size_t)n * TT + t) * HH + jg] = h;
            __nv_bfloat16 hh = __float2bfloat16(h);
            nhhi[ci] = hh;
            nhlo[ci] = __float2bfloat16(h - __bfloat162float(hh));
        }
    }
}

// ---------------------------------------------------------------------------
extern "C" void kernel_launch(void* const* d_in, const int* in_sizes, int n_in,
                              void* d_out, int out_size)
{
    const float* x  = (const float*)d_in[0];   // (64, 512, 1024)
    const float* h0 = (const float*)d_in[1];   // (64, 1024)
    const float* Wx = (const float*)d_in[2];   // (1024, 4096)
    const float* Wh = (const float*)d_in[3];   // (1024, 4096)
    const float* b  = (const float*)d_in[4];   // (4096,)
    float* out = (float*)d_out;                // (64, 512, 1024)

    cudaFuncSetAttribute(xw_gemm_mma,   cudaFuncAttributeMaxDynamicSharedMemorySize, G_SMEM);
    cudaFuncSetAttribute(lstm_step_mma, cudaFuncAttributeMaxDynamicSharedMemorySize, S_SMEM);

    __nv_bfloat16 *wxt_hi, *wxt_lo, *wht_hi, *wht_lo;
    cudaGetSymbolAddress((void**)&wxt_hi, g_wxt_hi);
    cudaGetSymbolAddress((void**)&wxt_lo, g_wxt_lo);
    cudaGetSymbolAddress((void**)&wht_hi, g_wht_hi);
    cudaGetSymbolAddress((void**)&wht_lo, g_wht_lo);

    prep_small_kernel<<<64, 1024>>>(h0, b);
    split_x_kernel<<<(NB * TT * DD / 4) / 256, 256>>>(x);
    transpose_split_kernel<<<dim3(DD / 32, FOURH / 32), dim3(32, 8)>>>(Wx, wxt_hi, wxt_lo);
    transpose_split_kernel<<<dim3(DD / 32, FOURH / 32), dim3(32, 8)>>>(Wh, wht_hi, wht_lo);

    xw_gemm_mma<<<dim3(32, 256), 256, G_SMEM>>>();

    for (int t = 0; t < TT; t++)
        lstm_step_mma<<<32, 512, S_SMEM>>>(t, out);
}

// round 5
// speedup vs baseline: 4.2978x; 2.2278x over previous
#include <cuda_runtime.h>
#include <cuda_bf16.h>
#include <math.h>
#include <stdint.h>

#define NB 64
#define TT 512
#define DD 1024
#define HH 1024
#define FOURH 4096
#define P_CTAS 128

// ---------------------------------------------------------------------------
// Scratch (__device__ globals; allocation-free rule)
// ---------------------------------------------------------------------------
__device__ float          g_xw[(size_t)NB * TT * FOURH];      // 512 MiB xW+b (permuted cols)
__device__ __nv_bfloat16  g_xhi[(size_t)NB * TT * DD];        // 64 MiB
__device__ __nv_bfloat16  g_xlo[(size_t)NB * TT * DD];        // 64 MiB
__device__ __nv_bfloat16  g_wxt_hi[(size_t)FOURH * DD];       // WxT perm [j'][k]
__device__ __nv_bfloat16  g_wxt_lo[(size_t)FOURH * DD];
__device__ __nv_bfloat16  g_wht_hi[(size_t)FOURH * DD];       // WhT perm [j'][k]
__device__ __nv_bfloat16  g_wht_lo[(size_t)FOURH * DD];
__device__ __nv_bfloat16  g_h_hi[2][NB * HH];                 // h double buffer (bf16 hi)
__device__ __nv_bfloat16  g_h_lo[2][NB * HH];                 // h double buffer (bf16 lo)
__device__ float          g_biasp[FOURH];                     // permuted bias
__device__ unsigned       g_bar;                              // global barrier counter

// ---------------------------------------------------------------------------
// Helpers
// ---------------------------------------------------------------------------
__device__ __forceinline__ uint32_t smem_u32(const void* p) {
    uint32_t a;
    asm("{ .reg .u64 t; cvta.to.shared.u64 t, %1; cvt.u32.u64 %0, t; }"
        : "=r"(a) : "l"(p));
    return a;
}

#define CP16(dst, src) \
    asm volatile("cp.async.cg.shared.global [%0], [%1], 16;" :: "r"(dst), "l"(src) : "memory")
#define CP_COMMIT() asm volatile("cp.async.commit_group;" ::: "memory")
#define CP_WAIT(n)  asm volatile("cp.async.wait_group %0;" :: "n"(n) : "memory")

#define LDSM4(r0, r1, r2, r3, addr) \
    asm volatile("ldmatrix.sync.aligned.m8n8.x4.shared.b16 {%0,%1,%2,%3}, [%4];" \
                 : "=r"(r0), "=r"(r1), "=r"(r2), "=r"(r3) : "r"(addr))

#define MMA_BF16(c0, c1, c2, c3, a0, a1, a2, a3, b0, b1) \
    asm volatile("mma.sync.aligned.m16n8k16.row.col.f32.bf16.bf16.f32 " \
                 "{%0,%1,%2,%3}, {%4,%5,%6,%7}, {%8,%9}, {%0,%1,%2,%3};" \
                 : "+f"(c0), "+f"(c1), "+f"(c2), "+f"(c3) \
                 : "r"(a0), "r"(a1), "r"(a2), "r"(a3), "r"(b0), "r"(b1))

__device__ __forceinline__ float fsigmoid(float x) { return 1.0f / (1.0f + __expf(-x)); }
__device__ __forceinline__ float ftanh(float x)    { return 2.0f / (1.0f + __expf(-2.0f * x)) - 1.0f; }

// ---------------------------------------------------------------------------
// Prep kernels
// ---------------------------------------------------------------------------
__global__ void prep_small_kernel(const float* __restrict__ h0, const float* __restrict__ b) {
    int i = blockIdx.x * 1024 + threadIdx.x;
    if (i == 0) g_bar = 0u;
    if (i < NB * HH) {
        float v = h0[i];
        __nv_bfloat16 hi = __float2bfloat16(v);
        g_h_hi[0][i] = hi;
        g_h_lo[0][i] = __float2bfloat16(v - __bfloat162float(hi));
    }
    if (i < FOURH) {
        int jp = (i & 1023) * 4 + (i >> 10);     // perm: col g*1024+jh -> jh*4+g
        g_biasp[jp] = b[i];
    }
}

__global__ void split_x_kernel(const float* __restrict__ x) {
    size_t i = ((size_t)blockIdx.x * 256 + threadIdx.x) * 4;
    float4 v = *(const float4*)(x + i);
    __nv_bfloat16 h0 = __float2bfloat16(v.x), h1 = __float2bfloat16(v.y);
    __nv_bfloat16 h2 = __float2bfloat16(v.z), h3 = __float2bfloat16(v.w);
    __nv_bfloat162* ph = (__nv_bfloat162*)(g_xhi + i);
    __nv_bfloat162* pl = (__nv_bfloat162*)(g_xlo + i);
    ph[0] = __nv_bfloat162(h0, h1);
    ph[1] = __nv_bfloat162(h2, h3);
    pl[0] = __nv_bfloat162(__float2bfloat16(v.x - __bfloat162float(h0)),
                           __float2bfloat16(v.y - __bfloat162float(h1)));
    pl[1] = __nv_bfloat162(__float2bfloat16(v.z - __bfloat162float(h2)),
                           __float2bfloat16(v.w - __bfloat162float(h3)));
}

// W (1024 x 4096, k-major rows) -> out[j'][k] bf16 hi/lo with gate permutation.
__global__ void transpose_split_kernel(const float* __restrict__ W,
                                       __nv_bfloat16* __restrict__ ohi,
                                       __nv_bfloat16* __restrict__ olo) {
    __shared__ float ts[32][33];
    const int k0 = blockIdx.x * 32;
    const int c0 = blockIdx.y * 32;
    const int tx = threadIdx.x, ty = threadIdx.y;  // 32 x 8
    #pragma unroll
    for (int i = 0; i < 4; i++)
        ts[ty + 8 * i][tx] = W[(size_t)(k0 + ty + 8 * i) * FOURH + c0 + tx];
    __syncthreads();
    #pragma unroll
    for (int i = 0; i < 4; i++) {
        int c = c0 + ty + 8 * i;
        int jp = (c & 1023) * 4 + (c >> 10);
        float v = ts[tx][ty + 8 * i];
        __nv_bfloat16 hi = __float2bfloat16(v);
        ohi[(size_t)jp * DD + k0 + tx] = hi;
        olo[(size_t)jp * DD + k0 + tx] = __float2bfloat16(v - __bfloat162float(hi));
    }
}

// ---------------------------------------------------------------------------
// xW GEMM via mma.sync (unchanged from R4 working version)
// ---------------------------------------------------------------------------
#define G_STAGE 65536   // Ah 16K | Al 16K | Bh 16K | Bl 16K
#define G_SMEM  (3 * G_STAGE)

__global__ __launch_bounds__(256, 1)
void xw_gemm_mma() {
    extern __shared__ char smem[];
    const uint32_t sb = smem_u32(smem);
    const int tid = threadIdx.x;
    const int nbase = blockIdx.x * 128;
    const int mbase = blockIdx.y * 128;

    const __nv_bfloat16* Ahg = g_xhi + (size_t)mbase * DD;
    const __nv_bfloat16* Alg = g_xlo + (size_t)mbase * DD;
    const __nv_bfloat16* Bhg = g_wxt_hi + (size_t)nbase * DD;
    const __nv_bfloat16* Blg = g_wxt_lo + (size_t)nbase * DD;

    auto cp_chunk = [&](int c, int st) {
        const int k0 = c * 64;
        const uint32_t ah = sb + st * G_STAGE;
        #pragma unroll
        for (int i = 0; i < 4; i++) {
            int idx = tid + i * 256;
            int row = idx >> 3, ch = idx & 7;
            uint32_t o = (uint32_t)(row * 128) + (uint32_t)((ch * 16) ^ ((row & 7) * 16));
            CP16(ah + o,         (const char*)(Ahg + (size_t)row * DD + k0) + ch * 16);
            CP16(ah + 16384 + o, (const char*)(Alg + (size_t)row * DD + k0) + ch * 16);
            CP16(ah + 32768 + o, (const char*)(Bhg + (size_t)row * DD + k0) + ch * 16);
            CP16(ah + 49152 + o, (const char*)(Blg + (size_t)row * DD + k0) + ch * 16);
        }
        CP_COMMIT();
    };

    const int wid = tid >> 5, lane = tid & 31;
    const int wm = wid >> 2, wn = wid & 3;      // warp grid 2x4
    const int m0 = wm * 64, n0 = wn * 32;
    const int gid = lane >> 2, tig = lane & 3;

    const int a_r = lane & 15;
    const uint32_t a_k = ((lane >> 4) & 1) * 16;
    const uint32_t a_x = (uint32_t)((a_r & 7) * 16);
    const int b_r = (lane & 7) + ((lane >> 4) & 1) * 8;
    const uint32_t b_k = ((lane >> 3) & 1) * 16;
    const uint32_t b_x = (uint32_t)((lane & 7) * 16);

    float acc[4][4][4];
    #pragma unroll
    for (int mt = 0; mt < 4; mt++)
        #pragma unroll
        for (int nt = 0; nt < 4; nt++)
            #pragma unroll
            for (int q = 0; q < 4; q++) acc[mt][nt][q] = 0.0f;

    cp_chunk(0, 0);
    cp_chunk(1, 1);

    for (int c = 0; c < 16; c++) {
        if (c + 2 < 16) { cp_chunk(c + 2, (c + 2) % 3); CP_WAIT(2); }
        else if (c + 1 < 16) { CP_WAIT(1); }
        else { CP_WAIT(0); }
        __syncthreads();

        const uint32_t base = sb + (c % 3) * G_STAGE;
        #pragma unroll
        for (int kk = 0; kk < 4; kk++) {
            const uint32_t ka = ((uint32_t)(kk * 32) + a_k) ^ a_x;
            const uint32_t kb = ((uint32_t)(kk * 32) + b_k) ^ b_x;
            uint32_t ah[4][4], al[4][4], bh[2][4], bl[2][4];
            #pragma unroll
            for (int mt = 0; mt < 4; mt++) {
                uint32_t ra = base + (uint32_t)((m0 + mt * 16 + a_r) * 128);
                LDSM4(ah[mt][0], ah[mt][1], ah[mt][2], ah[mt][3], ra + ka);
                LDSM4(al[mt][0], al[mt][1], al[mt][2], al[mt][3], ra + 16384 + ka);
            }
            #pragma unroll
            for (int p = 0; p < 2; p++) {
                uint32_t rb = base + 32768 + (uint32_t)((n0 + p * 16 + b_r) * 128);
                LDSM4(bh[p][0], bh[p][1], bh[p][2], bh[p][3], rb + kb);
                LDSM4(bl[p][0], bl[p][1], bl[p][2], bl[p][3], rb + 16384 + kb);
            }
            #pragma unroll
            for (int mt = 0; mt < 4; mt++)
                #pragma unroll
                for (int nt = 0; nt < 4; nt++) {
                    const int p = nt >> 1, hf = (nt & 1) * 2;
                    MMA_BF16(acc[mt][nt][0], acc[mt][nt][1], acc[mt][nt][2], acc[mt][nt][3],
                             ah[mt][0], ah[mt][1], ah[mt][2], ah[mt][3],
                             bh[p][hf], bh[p][hf + 1]);
                    MMA_BF16(acc[mt][nt][0], acc[mt][nt][1], acc[mt][nt][2], acc[mt][nt][3],
                             ah[mt][0], ah[mt][1], ah[mt][2], ah[mt][3],
                             bl[p][hf], bl[p][hf + 1]);
                    MMA_BF16(acc[mt][nt][0], acc[mt][nt][1], acc[mt][nt][2], acc[mt][nt][3],
                             al[mt][0], al[mt][1], al[mt][2], al[mt][3],
                             bh[p][hf], bh[p][hf + 1]);
                }
        }
        __syncthreads();
    }

    #pragma unroll
    for (int nt = 0; nt < 4; nt++) {
        const int col = nbase + n0 + nt * 8 + tig * 2;
        float2 bv = *(const float2*)&g_biasp[col];
        #pragma unroll
        for (int mt = 0; mt < 4; mt++) {
            const int row = mbase + m0 + mt * 16 + gid;
            float2 v0, v1;
            v0.x = acc[mt][nt][0] + bv.x; v0.y = acc[mt][nt][1] + bv.y;
            v1.x = acc[mt][nt][2] + bv.x; v1.y = acc[mt][nt][3] + bv.y;
            *(float2*)&g_xw[(size_t)row * FOURH + col] = v0;
            *(float2*)&g_xw[(size_t)(row + 8) * FOURH + col] = v1;
        }
    }
}

// ---------------------------------------------------------------------------
// Persistent LSTM recurrence kernel: all 512 steps in one launch.
// 128 CTAs x 256 threads (1 CTA/SM, all resident -> global barrier is safe).
// CTA jb owns j' in [jb*32, jb*32+32) = hidden units [jb*8, jb*8+8) x 4 gates.
// Wh slice (hi+lo, 128KB) persists in SMEM across all steps. c in registers.
// Per step: h (B operand) streamed via 4-stage cp.async pipeline; gates fused.
// ---------------------------------------------------------------------------
#define PA_HI  0                // 64KB: Wh_hi slice, 16 chunks x 4KB
#define PA_LO  65536            // 64KB: Wh_lo slice
#define PB     131072           // 4 stages x 16KB (h_hi 8K | h_lo 8K)
#define PXW    196608           // 8KB xw tile (64 n x 32 j')
#define PAS    204800           // a_s: 64 x 33 floats = 8448B
#define P_SMEM (204800 + 8448)  // 213248 bytes

__global__ __launch_bounds__(256, 1)
void lstm_persistent(float* __restrict__ out) {
    extern __shared__ char smem[];
    const uint32_t sb = smem_u32(smem);
    const int tid = threadIdx.x;
    const int jb = blockIdx.x;                 // 0..127
    const int wid = tid >> 5, lane = tid & 31;
    const int wm = wid >> 2, wn = wid & 3;     // warp grid 2(m) x 4(n)
    const int m0 = wm * 16, n0 = wn * 16;
    const int gid = lane >> 2, tig = lane & 3;

    const int a_r = lane & 15;
    const uint32_t a_k = ((lane >> 4) & 1) * 16;
    const uint32_t a_x = (uint32_t)((a_r & 7) * 16);
    const int b_r = (lane & 7) + ((lane >> 4) & 1) * 8;
    const uint32_t b_k = ((lane >> 3) & 1) * 16;
    const uint32_t b_x = (uint32_t)((lane & 7) * 16);

    // ---- load persistent Wh slice (16 k-chunks x 32 rows x 128B, hi+lo) ----
    {
        const __nv_bfloat16* Ahg = g_wht_hi + (size_t)jb * 32 * DD;
        const __nv_bfloat16* Alg = g_wht_lo + (size_t)jb * 32 * DD;
        #pragma unroll
        for (int i = 0; i < 16; i++) {
            int idx = tid + i * 256;
            int c = idx >> 8;
            int row = (idx >> 3) & 31;
            int ch = idx & 7;
            uint32_t o = (uint32_t)(c * 4096 + row * 128)
                       + (uint32_t)((ch * 16) ^ ((row & 7) * 16));
            CP16(sb + PA_HI + o, (const char*)(Ahg + (size_t)row * DD + c * 64) + ch * 16);
            CP16(sb + PA_LO + o, (const char*)(Alg + (size_t)row * DD + c * 64) + ch * 16);
        }
        CP_COMMIT();
        CP_WAIT(0);
        __syncthreads();
    }

    float creg[2] = {0.0f, 0.0f};   // cell state for this thread's 2 (n,jhl) pairs

    for (unsigned t = 0; t < TT; t++) {
        const __nv_bfloat16* Bhg = g_h_hi[t & 1];
        const __nv_bfloat16* Blg = g_h_lo[t & 1];

        auto cp_b = [&](int c, int st) {
            const int k0 = c * 64;
            const uint32_t bb = sb + PB + st * 16384;
            #pragma unroll
            for (int i = 0; i < 2; i++) {
                int idx = tid + i * 256;
                int row = idx >> 3, ch = idx & 7;
                uint32_t o = (uint32_t)(row * 128) + (uint32_t)((ch * 16) ^ ((row & 7) * 16));
                CP16(bb + o,        (const char*)(Bhg + (size_t)row * DD + k0) + ch * 16);
                CP16(bb + 8192 + o, (const char*)(Blg + (size_t)row * DD + k0) + ch * 16);
            }
            CP_COMMIT();
        };

        // xw tile prefetch (rides in group 0 with B chunk 0)
        #pragma unroll
        for (int i = 0; i < 2; i++) {
            int idx = tid + i * 256;
            int row = idx >> 3, ch = idx & 7;
            const char* src = (const char*)(g_xw + ((size_t)row * TT + t) * FOURH + jb * 32) + ch * 16;
            CP16(sb + PXW + (uint32_t)(row * 128 + ch * 16), src);
        }
        cp_b(0, 0);
        cp_b(1, 1);
        cp_b(2, 2);

        float acc[2][4];
        #pragma unroll
        for (int nt = 0; nt < 2; nt++)
            #pragma unroll
            for (int q = 0; q < 4; q++) acc[nt][q] = 0.0f;

        for (int c = 0; c < 16; c++) {
            if (c + 3 < 16) { cp_b(c + 3, (c + 3) & 3); CP_WAIT(3); }
            else if (c == 13) { CP_WAIT(2); }
            else if (c == 14) { CP_WAIT(1); }
            else { CP_WAIT(0); }
            __syncthreads();

            const uint32_t bstage = sb + PB + (uint32_t)((c & 3) * 16384);
            const uint32_t a_hi = sb + PA_HI + (uint32_t)(c * 4096);
            const uint32_t a_lo = sb + PA_LO + (uint32_t)(c * 4096);
            const uint32_t arow = (uint32_t)((m0 + a_r) * 128);
            const uint32_t brow = (uint32_t)((n0 + b_r) * 128);
            #pragma unroll
            for (int kk = 0; kk < 4; kk++) {
                const uint32_t ka = ((uint32_t)(kk * 32) + a_k) ^ a_x;
                const uint32_t kb = ((uint32_t)(kk * 32) + b_k) ^ b_x;
                uint32_t ah[4], al[4], bh[4], bl[4];
                LDSM4(ah[0], ah[1], ah[2], ah[3], a_hi + arow + ka);
                LDSM4(al[0], al[1], al[2], al[3], a_lo + arow + ka);
                LDSM4(bh[0], bh[1], bh[2], bh[3], bstage + brow + kb);
                LDSM4(bl[0], bl[1], bl[2], bl[3], bstage + 8192 + brow + kb);
                #pragma unroll
                for (int nt = 0; nt < 2; nt++) {
                    MMA_BF16(acc[nt][0], acc[nt][1], acc[nt][2], acc[nt][3],
                             ah[0], ah[1], ah[2], ah[3], bh[nt * 2], bh[nt * 2 + 1]);
                    MMA_BF16(acc[nt][0], acc[nt][1], acc[nt][2], acc[nt][3],
                             ah[0], ah[1], ah[2], ah[3], bl[nt * 2], bl[nt * 2 + 1]);
                    MMA_BF16(acc[nt][0], acc[nt][1], acc[nt][2], acc[nt][3],
                             al[0], al[1], al[2], al[3], bh[nt * 2], bh[nt * 2 + 1]);
                }
            }
            __syncthreads();
        }

        // stage preactivations: a_s[n][j'l], stride 33 floats (conflict-free)
        float* a_s = (float*)(smem + PAS);
        #pragma unroll
        for (int nt = 0; nt < 2; nt++) {
            const int n = n0 + nt * 8 + tig * 2;
            const int j = m0 + gid;
            a_s[n * 33 + j]           = acc[nt][0];
            a_s[(n + 1) * 33 + j]     = acc[nt][1];
            a_s[n * 33 + j + 8]       = acc[nt][2];
            a_s[(n + 1) * 33 + j + 8] = acc[nt][3];
        }
        __syncthreads();

        // fused gates + c/h update (c in registers)
        {
            const float* xws = (const float*)(smem + PXW);
            __nv_bfloat16* nhhi = g_h_hi[(t + 1) & 1];
            __nv_bfloat16* nhlo = g_h_lo[(t + 1) & 1];
            #pragma unroll
            for (int i = 0; i < 2; i++) {
                const int p = tid + i * 256;
                const int n = p >> 3;        // 0..63
                const int jhl = p & 7;       // 0..7
                const float* ar = a_s + n * 33 + jhl * 4;
                const float* xr = xws + n * 32 + jhl * 4;
                float ig = fsigmoid(ar[0] + xr[0]);
                float fg = fsigmoid(ar[1] + xr[1]);
                float og = fsigmoid(ar[2] + xr[2]);
                float gg = ftanh(ar[3] + xr[3]);
                float cn = fg * creg[i] + ig * gg;
                creg[i] = cn;
                float h = og * ftanh(cn);
                const int jg = jb * 8 + jhl;
                out[((size_t)n * TT + t) * HH + jg] = h;
                __nv_bfloat16 hh = __float2bfloat16(h);
                const int hidx = n * HH + jg;
                nhhi[hidx] = hh;
                nhlo[hidx] = __float2bfloat16(h - __bfloat162float(hh));
            }
        }

        // global barrier (monotonic counter; 128 CTAs all resident)
        __syncthreads();
        if (tid == 0) {
            __threadfence();
            atomicAdd(&g_bar, 1u);
            const unsigned target = (t + 1u) * (unsigned)P_CTAS;
            while (*(volatile unsigned*)&g_bar < target) { }
            __threadfence();
        }
        __syncthreads();
    }
}

// ---------------------------------------------------------------------------
extern "C" void kernel_launch(void* const* d_in, const int* in_sizes, int n_in,
                              void* d_out, int out_size)
{
    const float* x  = (const float*)d_in[0];   // (64, 512, 1024)
    const float* h0 = (const float*)d_in[1];   // (64, 1024)
    const float* Wx = (const float*)d_in[2];   // (1024, 4096)
    const float* Wh = (const float*)d_in[3];   // (1024, 4096)
    const float* b  = (const float*)d_in[4];   // (4096,)
    float* out = (float*)d_out;                // (64, 512, 1024)

    cudaFuncSetAttribute(xw_gemm_mma,     cudaFuncAttributeMaxDynamicSharedMemorySize, G_SMEM);
    cudaFuncSetAttribute(lstm_persistent, cudaFuncAttributeMaxDynamicSharedMemorySize, P_SMEM);

    __nv_bfloat16 *wxt_hi, *wxt_lo, *wht_hi, *wht_lo;
    cudaGetSymbolAddress((void**)&wxt_hi, g_wxt_hi);
    cudaGetSymbolAddress((void**)&wxt_lo, g_wxt_lo);
    cudaGetSymbolAddress((void**)&wht_hi, g_wht_hi);
    cudaGetSymbolAddress((void**)&wht_lo, g_wht_lo);

    prep_small_kernel<<<64, 1024>>>(h0, b);
    split_x_kernel<<<(NB * TT * DD / 4) / 256, 256>>>(x);
    transpose_split_kernel<<<dim3(DD / 32, FOURH / 32), dim3(32, 8)>>>(Wx, wxt_hi, wxt_lo);
    transpose_split_kernel<<<dim3(DD / 32, FOURH / 32), dim3(32, 8)>>>(Wh, wht_hi, wht_lo);

    xw_gemm_mma<<<dim3(32, 256), 256, G_SMEM>>>();

    lstm_persistent<<<P_CTAS, 256, P_SMEM>>>(out);
}

// round 6
// speedup vs baseline: 4.5935x; 1.0688x over previous
#include <cuda_runtime.h>
#include <cuda_bf16.h>
#include <math.h>
#include <stdint.h>

#define NB 64
#define TT 512
#define DD 1024
#define HH 1024
#define FOURH 4096
#define P_CTAS 128

// ---------------------------------------------------------------------------
// Scratch (__device__ globals; allocation-free rule)
// ---------------------------------------------------------------------------
__device__ float          g_xw[(size_t)NB * TT * FOURH];      // 512 MiB xW+b (permuted cols)
__device__ __nv_bfloat16  g_xhi[(size_t)NB * TT * DD];        // 64 MiB
__device__ __nv_bfloat16  g_xlo[(size_t)NB * TT * DD];        // 64 MiB
__device__ __nv_bfloat16  g_wxt_hi[(size_t)FOURH * DD];       // WxT perm [j'][k]
__device__ __nv_bfloat16  g_wxt_lo[(size_t)FOURH * DD];
__device__ __nv_bfloat16  g_wht_hi[(size_t)FOURH * DD];       // WhT perm [j'][k]
__device__ __nv_bfloat16  g_wht_lo[(size_t)FOURH * DD];
__device__ __nv_bfloat16  g_h_hi[2][NB * HH];                 // h double buffer (bf16 hi)
__device__ __nv_bfloat16  g_h_lo[2][NB * HH];                 // h double buffer (bf16 lo)
__device__ float          g_biasp[FOURH];                     // permuted bias
__device__ unsigned       g_bar;                              // global barrier counter

// ---------------------------------------------------------------------------
// Helpers
// ---------------------------------------------------------------------------
__device__ __forceinline__ uint32_t smem_u32(const void* p) {
    uint32_t a;
    asm("{ .reg .u64 t; cvta.to.shared.u64 t, %1; cvt.u32.u64 %0, t; }"
        : "=r"(a) : "l"(p));
    return a;
}

#define CP16(dst, src) \
    asm volatile("cp.async.cg.shared.global [%0], [%1], 16;" :: "r"(dst), "l"(src) : "memory")
#define CP_COMMIT() asm volatile("cp.async.commit_group;" ::: "memory")
#define CP_WAIT(n)  asm volatile("cp.async.wait_group %0;" :: "n"(n) : "memory")

#define LDSM4(r0, r1, r2, r3, addr) \
    asm volatile("ldmatrix.sync.aligned.m8n8.x4.shared.b16 {%0,%1,%2,%3}, [%4];" \
                 : "=r"(r0), "=r"(r1), "=r"(r2), "=r"(r3) : "r"(addr))

#define MMA_BF16(c0, c1, c2, c3, a0, a1, a2, a3, b0, b1) \
    asm volatile("mma.sync.aligned.m16n8k16.row.col.f32.bf16.bf16.f32 " \
                 "{%0,%1,%2,%3}, {%4,%5,%6,%7}, {%8,%9}, {%0,%1,%2,%3};" \
                 : "+f"(c0), "+f"(c1), "+f"(c2), "+f"(c3) \
                 : "r"(a0), "r"(a1), "r"(a2), "r"(a3), "r"(b0), "r"(b1))

__device__ __forceinline__ float fsigmoid(float x) { return 1.0f / (1.0f + __expf(-x)); }
__device__ __forceinline__ float ftanh(float x)    { return 2.0f / (1.0f + __expf(-2.0f * x)) - 1.0f; }

// ---------------------------------------------------------------------------
// Prep kernels
// ---------------------------------------------------------------------------
__global__ void prep_small_kernel(const float* __restrict__ h0, const float* __restrict__ b) {
    int i = blockIdx.x * 1024 + threadIdx.x;
    if (i == 0) g_bar = 0u;
    if (i < NB * HH) {
        float v = h0[i];
        __nv_bfloat16 hi = __float2bfloat16(v);
        g_h_hi[0][i] = hi;
        g_h_lo[0][i] = __float2bfloat16(v - __bfloat162float(hi));
    }
    if (i < FOURH) {
        int jp = (i & 1023) * 4 + (i >> 10);     // perm: col g*1024+jh -> jh*4+g
        g_biasp[jp] = b[i];
    }
}

__global__ void split_x_kernel(const float* __restrict__ x) {
    size_t i = ((size_t)blockIdx.x * 256 + threadIdx.x) * 4;
    float4 v = *(const float4*)(x + i);
    __nv_bfloat16 h0 = __float2bfloat16(v.x), h1 = __float2bfloat16(v.y);
    __nv_bfloat16 h2 = __float2bfloat16(v.z), h3 = __float2bfloat16(v.w);
    __nv_bfloat162* ph = (__nv_bfloat162*)(g_xhi + i);
    __nv_bfloat162* pl = (__nv_bfloat162*)(g_xlo + i);
    ph[0] = __nv_bfloat162(h0, h1);
    ph[1] = __nv_bfloat162(h2, h3);
    pl[0] = __nv_bfloat162(__float2bfloat16(v.x - __bfloat162float(h0)),
                           __float2bfloat16(v.y - __bfloat162float(h1)));
    pl[1] = __nv_bfloat162(__float2bfloat16(v.z - __bfloat162float(h2)),
                           __float2bfloat16(v.w - __bfloat162float(h3)));
}

// W (1024 x 4096, k-major rows) -> out[j'][k] bf16 hi/lo with gate permutation.
__global__ void transpose_split_kernel(const float* __restrict__ W,
                                       __nv_bfloat16* __restrict__ ohi,
                                       __nv_bfloat16* __restrict__ olo) {
    __shared__ float ts[32][33];
    const int k0 = blockIdx.x * 32;
    const int c0 = blockIdx.y * 32;
    const int tx = threadIdx.x, ty = threadIdx.y;  // 32 x 8
    #pragma unroll
    for (int i = 0; i < 4; i++)
        ts[ty + 8 * i][tx] = W[(size_t)(k0 + ty + 8 * i) * FOURH + c0 + tx];
    __syncthreads();
    #pragma unroll
    for (int i = 0; i < 4; i++) {
        int c = c0 + ty + 8 * i;
        int jp = (c & 1023) * 4 + (c >> 10);
        float v = ts[tx][ty + 8 * i];
        __nv_bfloat16 hi = __float2bfloat16(v);
        ohi[(size_t)jp * DD + k0 + tx] = hi;
        olo[(size_t)jp * DD + k0 + tx] = __float2bfloat16(v - __bfloat162float(hi));
    }
}

// ---------------------------------------------------------------------------
// xW GEMM via mma.sync (unchanged working version)
// ---------------------------------------------------------------------------
#define G_STAGE 65536   // Ah 16K | Al 16K | Bh 16K | Bl 16K
#define G_SMEM  (3 * G_STAGE)

__global__ __launch_bounds__(256, 1)
void xw_gemm_mma() {
    extern __shared__ char smem[];
    const uint32_t sb = smem_u32(smem);
    const int tid = threadIdx.x;
    const int nbase = blockIdx.x * 128;
    const int mbase = blockIdx.y * 128;

    const __nv_bfloat16* Ahg = g_xhi + (size_t)mbase * DD;
    const __nv_bfloat16* Alg = g_xlo + (size_t)mbase * DD;
    const __nv_bfloat16* Bhg = g_wxt_hi + (size_t)nbase * DD;
    const __nv_bfloat16* Blg = g_wxt_lo + (size_t)nbase * DD;

    auto cp_chunk = [&](int c, int st) {
        const int k0 = c * 64;
        const uint32_t ah = sb + st * G_STAGE;
        #pragma unroll
        for (int i = 0; i < 4; i++) {
            int idx = tid + i * 256;
            int row = idx >> 3, ch = idx & 7;
            uint32_t o = (uint32_t)(row * 128) + (uint32_t)((ch * 16) ^ ((row & 7) * 16));
            CP16(ah + o,         (const char*)(Ahg + (size_t)row * DD + k0) + ch * 16);
            CP16(ah + 16384 + o, (const char*)(Alg + (size_t)row * DD + k0) + ch * 16);
            CP16(ah + 32768 + o, (const char*)(Bhg + (size_t)row * DD + k0) + ch * 16);
            CP16(ah + 49152 + o, (const char*)(Blg + (size_t)row * DD + k0) + ch * 16);
        }
        CP_COMMIT();
    };

    const int wid = tid >> 5, lane = tid & 31;
    const int wm = wid >> 2, wn = wid & 3;      // warp grid 2x4
    const int m0 = wm * 64, n0 = wn * 32;
    const int gid = lane >> 2, tig = lane & 3;

    const int a_r = lane & 15;
    const uint32_t a_k = ((lane >> 4) & 1) * 16;
    const uint32_t a_x = (uint32_t)((a_r & 7) * 16);
    const int b_r = (lane & 7) + ((lane >> 4) & 1) * 8;
    const uint32_t b_k = ((lane >> 3) & 1) * 16;
    const uint32_t b_x = (uint32_t)((lane & 7) * 16);

    float acc[4][4][4];
    #pragma unroll
    for (int mt = 0; mt < 4; mt++)
        #pragma unroll
        for (int nt = 0; nt < 4; nt++)
            #pragma unroll
            for (int q = 0; q < 4; q++) acc[mt][nt][q] = 0.0f;

    cp_chunk(0, 0);
    cp_chunk(1, 1);

    for (int c = 0; c < 16; c++) {
        if (c + 2 < 16) { cp_chunk(c + 2, (c + 2) % 3); CP_WAIT(2); }
        else if (c + 1 < 16) { CP_WAIT(1); }
        else { CP_WAIT(0); }
        __syncthreads();

        const uint32_t base = sb + (c % 3) * G_STAGE;
        #pragma unroll
        for (int kk = 0; kk < 4; kk++) {
            const uint32_t ka = ((uint32_t)(kk * 32) + a_k) ^ a_x;
            const uint32_t kb = ((uint32_t)(kk * 32) + b_k) ^ b_x;
            uint32_t ah[4][4], al[4][4], bh[2][4], bl[2][4];
            #pragma unroll
            for (int mt = 0; mt < 4; mt++) {
                uint32_t ra = base + (uint32_t)((m0 + mt * 16 + a_r) * 128);
                LDSM4(ah[mt][0], ah[mt][1], ah[mt][2], ah[mt][3], ra + ka);
                LDSM4(al[mt][0], al[mt][1], al[mt][2], al[mt][3], ra + 16384 + ka);
            }
            #pragma unroll
            for (int p = 0; p < 2; p++) {
                uint32_t rb = base + 32768 + (uint32_t)((n0 + p * 16 + b_r) * 128);
                LDSM4(bh[p][0], bh[p][1], bh[p][2], bh[p][3], rb + kb);
                LDSM4(bl[p][0], bl[p][1], bl[p][2], bl[p][3], rb + 16384 + kb);
            }
            #pragma unroll
            for (int mt = 0; mt < 4; mt++)
                #pragma unroll
                for (int nt = 0; nt < 4; nt++) {
                    const int p = nt >> 1, hf = (nt & 1) * 2;
                    MMA_BF16(acc[mt][nt][0], acc[mt][nt][1], acc[mt][nt][2], acc[mt][nt][3],
                             ah[mt][0], ah[mt][1], ah[mt][2], ah[mt][3],
                             bh[p][hf], bh[p][hf + 1]);
                    MMA_BF16(acc[mt][nt][0], acc[mt][nt][1], acc[mt][nt][2], acc[mt][nt][3],
                             ah[mt][0], ah[mt][1], ah[mt][2], ah[mt][3],
                             bl[p][hf], bl[p][hf + 1]);
                    MMA_BF16(acc[mt][nt][0], acc[mt][nt][1], acc[mt][nt][2], acc[mt][nt][3],
                             al[mt][0], al[mt][1], al[mt][2], al[mt][3],
                             bh[p][hf], bh[p][hf + 1]);
                }
        }
        __syncthreads();
    }

    #pragma unroll
    for (int nt = 0; nt < 4; nt++) {
        const int col = nbase + n0 + nt * 8 + tig * 2;
        float2 bv = *(const float2*)&g_biasp[col];
        #pragma unroll
        for (int mt = 0; mt < 4; mt++) {
            const int row = mbase + m0 + mt * 16 + gid;
            float2 v0, v1;
            v0.x = acc[mt][nt][0] + bv.x; v0.y = acc[mt][nt][1] + bv.y;
            v1.x = acc[mt][nt][2] + bv.x; v1.y = acc[mt][nt][3] + bv.y;
            *(float2*)&g_xw[(size_t)row * FOURH + col] = v0;
            *(float2*)&g_xw[(size_t)(row + 8) * FOURH + col] = v1;
        }
    }
}

// ---------------------------------------------------------------------------
// Persistent LSTM recurrence: warp-autonomous mainloop (NO block syncs inside).
// 128 CTAs x 256 threads. CTA jb owns j' [jb*32, jb*32+32) (8 hidden x 4 gates).
// Warp w owns batch rows n in [w*8, w*8+8): loads its own h rows + xw rows,
// computes m32 x n8 with private cp.async pipeline, does warp-local gates.
// ---------------------------------------------------------------------------
#define PA_HI  0                 // 64KB Wh_hi slice, 16 chunks x 4KB
#define PA_LO  65536             // 64KB Wh_lo slice
#define PB     131072            // 4 stages x 16KB (h_hi 8K | h_lo 8K)
#define PXW    196608            // 8KB xw tile (64 n x 32 j')
#define PASW   204800            // 8 warps x 1152B staging
#define P_SMEM (204800 + 9216)

__global__ __launch_bounds__(256, 1)
void lstm_persistent(float* __restrict__ out) {
    extern __shared__ char smem[];
    const uint32_t sb = smem_u32(smem);
    const int tid = threadIdx.x;
    const int jb = blockIdx.x;                 // 0..127
    const int wid = tid >> 5, lane = tid & 31;
    const int n0 = wid * 8;                    // warp's batch rows
    const int gid = lane >> 2, tig = lane & 3;

    // A (Wh) ldmatrix addressing
    const int a_r = lane & 15;
    const uint32_t a_k = ((lane >> 4) & 1) * 16;
    const uint32_t a_x = (uint32_t)((a_r & 7) * 16);
    // B ldmatrix addressing (n8 x k32 via x4)
    const int b_row = lane & 7;
    const int b_mat = lane >> 3;

    // ---- load persistent Wh slice (16 k-chunks x 32 rows x 128B, hi+lo) ----
    {
        const __nv_bfloat16* Ahg = g_wht_hi + (size_t)jb * 32 * DD;
        const __nv_bfloat16* Alg = g_wht_lo + (size_t)jb * 32 * DD;
        #pragma unroll
        for (int i = 0; i < 16; i++) {
            int idx = tid + i * 256;
            int c = idx >> 8;
            int row = (idx >> 3) & 31;
            int ch = idx & 7;
            uint32_t o = (uint32_t)(c * 4096 + row * 128)
                       + (uint32_t)((ch * 16) ^ ((row & 7) * 16));
            CP16(sb + PA_HI + o, (const char*)(Ahg + (size_t)row * DD + c * 64) + ch * 16);
            CP16(sb + PA_LO + o, (const char*)(Alg + (size_t)row * DD + c * 64) + ch * 16);
        }
        CP_COMMIT();
        CP_WAIT(0);
        __syncthreads();
    }

    float creg[2] = {0.0f, 0.0f};

    for (unsigned t = 0; t < TT; t++) {
        const __nv_bfloat16* Bhg = g_h_hi[t & 1];
        const __nv_bfloat16* Blg = g_h_lo[t & 1];

        // warp-private B chunk load: 8 rows x 64 k (hi+lo), 4 cp/lane
        auto cp_b = [&](int c, int st) {
            const int k0 = c * 64;
            const uint32_t bb = sb + PB + (uint32_t)(st * 16384);
            #pragma unroll
            for (int q = 0; q < 2; q++) {
                int idx = lane + q * 32;      // 0..63
                int row = idx >> 3;           // 0..7
                int ch = idx & 7;
                uint32_t o = (uint32_t)((n0 + row) * 128) + (uint32_t)((ch * 16) ^ (row * 16));
                CP16(bb + o,        (const char*)(Bhg + (size_t)(n0 + row) * DD + k0) + ch * 16);
                CP16(bb + 8192 + o, (const char*)(Blg + (size_t)(n0 + row) * DD + k0) + ch * 16);
            }
        };

        // group 0: warp's xw rows + B chunk 0
        #pragma unroll
        for (int q = 0; q < 2; q++) {
            int idx = lane + q * 32;
            int row = idx >> 3, ch = idx & 7;
            CP16(sb + PXW + (uint32_t)((n0 + row) * 128 + ch * 16),
                 (const char*)(g_xw + ((size_t)(n0 + row) * TT + t) * FOURH + jb * 32) + ch * 16);
        }
        cp_b(0, 0); CP_COMMIT();
        cp_b(1, 1); CP_COMMIT();
        cp_b(2, 2); CP_COMMIT();

        float acc[2][4];
        #pragma unroll
        for (int mt = 0; mt < 2; mt++)
            #pragma unroll
            for (int q = 0; q < 4; q++) acc[mt][q] = 0.0f;

        for (int c = 0; c < 16; c++) {
            if (c + 3 < 16)      { cp_b(c + 3, (c + 3) & 3); CP_COMMIT(); CP_WAIT(3); }
            else if (c == 13)    { CP_WAIT(2); }
            else if (c == 14)    { CP_WAIT(1); }
            else                 { CP_WAIT(0); }
            __syncwarp();

            const uint32_t bst = sb + PB + (uint32_t)((c & 3) * 16384);
            const uint32_t ahc = sb + PA_HI + (uint32_t)(c * 4096);
            const uint32_t alc = sb + PA_LO + (uint32_t)(c * 4096);
            #pragma unroll
            for (int k2 = 0; k2 < 2; k2++) {
                uint32_t bh[4], bl[4];
                const uint32_t bo = (uint32_t)((n0 + b_row) * 128)
                                  + (uint32_t)((k2 * 64 + b_mat * 16) ^ (b_row * 16));
                LDSM4(bh[0], bh[1], bh[2], bh[3], bst + bo);
                LDSM4(bl[0], bl[1], bl[2], bl[3], bst + 8192 + bo);
                #pragma unroll
                for (int hf = 0; hf < 2; hf++) {
                    const int kk = k2 * 2 + hf;
                    const uint32_t ka = ((uint32_t)(kk * 32) + a_k) ^ a_x;
                    #pragma unroll
                    for (int mt = 0; mt < 2; mt++) {
                        uint32_t ah[4], al[4];
                        const uint32_t ao = (uint32_t)((mt * 16 + a_r) * 128) + ka;
                        LDSM4(ah[0], ah[1], ah[2], ah[3], ahc + ao);
                        LDSM4(al[0], al[1], al[2], al[3], alc + ao);
                        MMA_BF16(acc[mt][0], acc[mt][1], acc[mt][2], acc[mt][3],
                                 ah[0], ah[1], ah[2], ah[3], bh[hf * 2], bh[hf * 2 + 1]);
                        MMA_BF16(acc[mt][0], acc[mt][1], acc[mt][2], acc[mt][3],
                                 ah[0], ah[1], ah[2], ah[3], bl[hf * 2], bl[hf * 2 + 1]);
                        MMA_BF16(acc[mt][0], acc[mt][1], acc[mt][2], acc[mt][3],
                                 al[0], al[1], al[2], al[3], bh[hf * 2], bh[hf * 2 + 1]);
                    }
                }
            }
        }

        // warp-local epilogue: stage acc -> asw[n_local][j'] (stride 36), gates
        float* asw = (float*)(smem + PASW + wid * 1152);
        #pragma unroll
        for (int mt = 0; mt < 2; mt++) {
            asw[(tig * 2 + 0) * 36 + mt * 16 + gid]     = acc[mt][0];
            asw[(tig * 2 + 1) * 36 + mt * 16 + gid]     = acc[mt][1];
            asw[(tig * 2 + 0) * 36 + mt * 16 + gid + 8] = acc[mt][2];
            asw[(tig * 2 + 1) * 36 + mt * 16 + gid + 8] = acc[mt][3];
        }
        __syncwarp();

        {
            const float* xws = (const float*)(smem + PXW);
            __nv_bfloat16* nhhi = g_h_hi[(t + 1) & 1];
            __nv_bfloat16* nhlo = g_h_lo[(t + 1) & 1];
            #pragma unroll
            for (int i = 0; i < 2; i++) {
                const int p = lane + i * 32;    // 0..63
                const int nl = p >> 3;          // 0..7
                const int jhl = p & 7;          // 0..7
                const float* ar = asw + nl * 36 + jhl * 4;
                const float* xr = xws + (n0 + nl) * 32 + jhl * 4;
                float ig = fsigmoid(ar[0] + xr[0]);
                float fg = fsigmoid(ar[1] + xr[1]);
                float og = fsigmoid(ar[2] + xr[2]);
                float gg = ftanh(ar[3] + xr[3]);
                float cn = fg * creg[i] + ig * gg;
                creg[i] = cn;
                float h = og * ftanh(cn);
                const int n = n0 + nl;
                const int jg = jb * 8 + jhl;
                out[((size_t)n * TT + t) * HH + jg] = h;
                __nv_bfloat16 hh = __float2bfloat16(h);
                const int hidx = n * HH + jg;
                nhhi[hidx] = hh;
                nhlo[hidx] = __float2bfloat16(h - __bfloat162float(hh));
            }
        }

        // global barrier (128 CTAs, all resident)
        __syncthreads();
        if (tid == 0) {
            __threadfence();
            atomicAdd(&g_bar, 1u);
            const unsigned target = (t + 1u) * (unsigned)P_CTAS;
            while (*(volatile unsigned*)&g_bar < target) { }
            __threadfence();
        }
        __syncthreads();
    }
}

// ---------------------------------------------------------------------------
extern "C" void kernel_launch(void* const* d_in, const int* in_sizes, int n_in,
                              void* d_out, int out_size)
{
    const float* x  = (const float*)d_in[0];   // (64, 512, 1024)
    const float* h0 = (const float*)d_in[1];   // (64, 1024)
    const float* Wx = (const float*)d_in[2];   // (1024, 4096)
    const float* Wh = (const float*)d_in[3];   // (1024, 4096)
    const float* b  = (const float*)d_in[4];   // (4096,)
    float* out = (float*)d_out;                // (64, 512, 1024)

    cudaFuncSetAttribute(xw_gemm_mma,     cudaFuncAttributeMaxDynamicSharedMemorySize, G_SMEM);
    cudaFuncSetAttribute(lstm_persistent, cudaFuncAttributeMaxDynamicSharedMemorySize, P_SMEM);

    __nv_bfloat16 *wxt_hi, *wxt_lo, *wht_hi, *wht_lo;
    cudaGetSymbolAddress((void**)&wxt_hi, g_wxt_hi);
    cudaGetSymbolAddress((void**)&wxt_lo, g_wxt_lo);
    cudaGetSymbolAddress((void**)&wht_hi, g_wht_hi);
    cudaGetSymbolAddress((void**)&wht_lo, g_wht_lo);

    prep_small_kernel<<<64, 1024>>>(h0, b);
    split_x_kernel<<<(NB * TT * DD / 4) / 256, 256>>>(x);
    transpose_split_kernel<<<dim3(DD / 32, FOURH / 32), dim3(32, 8)>>>(Wx, wxt_hi, wxt_lo);
    transpose_split_kernel<<<dim3(DD / 32, FOURH / 32), dim3(32, 8)>>>(Wh, wht_hi, wht_lo);

    xw_gemm_mma<<<dim3(32, 256), 256, G_SMEM>>>();

    lstm_persistent<<<P_CTAS, 256, P_SMEM>>>(out);
}

// round 7
// speedup vs baseline: 4.6028x; 1.0020x over previous
#include <cuda_runtime.h>
#include <cuda_bf16.h>
#include <math.h>
#include <stdint.h>

#define NB 64
#define TT 512
#define DD 1024
#define HH 1024
#define FOURH 4096
#define P_CTAS 128

// ---------------------------------------------------------------------------
// Scratch (__device__ globals; allocation-free rule)
// ---------------------------------------------------------------------------
__device__ float          g_xw[(size_t)NB * TT * FOURH];      // 512 MiB xW+b (permuted cols)
__device__ __nv_bfloat16  g_xhi[(size_t)NB * TT * DD];        // 64 MiB
__device__ __nv_bfloat16  g_xlo[(size_t)NB * TT * DD];        // 64 MiB
__device__ __nv_bfloat16  g_wxt_hi[(size_t)FOURH * DD];       // WxT perm [j'][k]
__device__ __nv_bfloat16  g_wxt_lo[(size_t)FOURH * DD];
__device__ __nv_bfloat16  g_wht_hi[(size_t)FOURH * DD];       // WhT perm [j'][k]
__device__ __nv_bfloat16  g_wht_lo[(size_t)FOURH * DD];
__device__ __nv_bfloat16  g_h_hi[2][NB * HH];                 // h double buffer (bf16 hi)
__device__ __nv_bfloat16  g_h_lo[2][NB * HH];                 // h double buffer (bf16 lo)
__device__ float          g_biasp[FOURH];                     // permuted bias
__device__ unsigned       g_bar;                              // global barrier counter

// ---------------------------------------------------------------------------
// Helpers
// ---------------------------------------------------------------------------
__device__ __forceinline__ uint32_t smem_u32(const void* p) {
    uint32_t a;
    asm("{ .reg .u64 t; cvta.to.shared.u64 t, %1; cvt.u32.u64 %0, t; }"
        : "=r"(a) : "l"(p));
    return a;
}

#define CP16(dst, src) \
    asm volatile("cp.async.cg.shared.global [%0], [%1], 16;" :: "r"(dst), "l"(src) : "memory")
#define CP_COMMIT() asm volatile("cp.async.commit_group;" ::: "memory")
#define CP_WAIT(n)  asm volatile("cp.async.wait_group %0;" :: "n"(n) : "memory")

#define LDSM4(r0, r1, r2, r3, addr) \
    asm volatile("ldmatrix.sync.aligned.m8n8.x4.shared.b16 {%0,%1,%2,%3}, [%4];" \
                 : "=r"(r0), "=r"(r1), "=r"(r2), "=r"(r3) : "r"(addr))

#define MMA_BF16(c0, c1, c2, c3, a0, a1, a2, a3, b0, b1) \
    asm volatile("mma.sync.aligned.m16n8k16.row.col.f32.bf16.bf16.f32 " \
                 "{%0,%1,%2,%3}, {%4,%5,%6,%7}, {%8,%9}, {%0,%1,%2,%3};" \
                 : "+f"(c0), "+f"(c1), "+f"(c2), "+f"(c3) \
                 : "r"(a0), "r"(a1), "r"(a2), "r"(a3), "r"(b0), "r"(b1))

__device__ __forceinline__ float fsigmoid(float x) { return 1.0f / (1.0f + __expf(-x)); }
__device__ __forceinline__ float ftanh(float x)    { return 2.0f / (1.0f + __expf(-2.0f * x)) - 1.0f; }

// ---------------------------------------------------------------------------
// Prep kernels
// ---------------------------------------------------------------------------
__global__ void prep_small_kernel(const float* __restrict__ h0, const float* __restrict__ b) {
    int i = blockIdx.x * 1024 + threadIdx.x;
    if (i == 0) g_bar = 0u;
    if (i < NB * HH) {
        float v = h0[i];
        __nv_bfloat16 hi = __float2bfloat16(v);
        g_h_hi[0][i] = hi;
        g_h_lo[0][i] = __float2bfloat16(v - __bfloat162float(hi));
    }
    if (i < FOURH) {
        int jp = (i & 1023) * 4 + (i >> 10);     // perm: col g*1024+jh -> jh*4+g
        g_biasp[jp] = b[i];
    }
}

__global__ void split_x_kernel(const float* __restrict__ x) {
    size_t i = ((size_t)blockIdx.x * 256 + threadIdx.x) * 4;
    float4 v = *(const float4*)(x + i);
    __nv_bfloat16 h0 = __float2bfloat16(v.x), h1 = __float2bfloat16(v.y);
    __nv_bfloat16 h2 = __float2bfloat16(v.z), h3 = __float2bfloat16(v.w);
    __nv_bfloat162* ph = (__nv_bfloat162*)(g_xhi + i);
    __nv_bfloat162* pl = (__nv_bfloat162*)(g_xlo + i);
    ph[0] = __nv_bfloat162(h0, h1);
    ph[1] = __nv_bfloat162(h2, h3);
    pl[0] = __nv_bfloat162(__float2bfloat16(v.x - __bfloat162float(h0)),
                           __float2bfloat16(v.y - __bfloat162float(h1)));
    pl[1] = __nv_bfloat162(__float2bfloat16(v.z - __bfloat162float(h2)),
                           __float2bfloat16(v.w - __bfloat162float(h3)));
}

// W (1024 x 4096, k-major rows) -> out[j'][k] bf16 hi/lo with gate permutation.
__global__ void transpose_split_kernel(const float* __restrict__ W,
                                       __nv_bfloat16* __restrict__ ohi,
                                       __nv_bfloat16* __restrict__ olo) {
    __shared__ float ts[32][33];
    const int k0 = blockIdx.x * 32;
    const int c0 = blockIdx.y * 32;
    const int tx = threadIdx.x, ty = threadIdx.y;  // 32 x 8
    #pragma unroll
    for (int i = 0; i < 4; i++)
        ts[ty + 8 * i][tx] = W[(size_t)(k0 + ty + 8 * i) * FOURH + c0 + tx];
    __syncthreads();
    #pragma unroll
    for (int i = 0; i < 4; i++) {
        int c = c0 + ty + 8 * i;
        int jp = (c & 1023) * 4 + (c >> 10);
        float v = ts[tx][ty + 8 * i];
        __nv_bfloat16 hi = __float2bfloat16(v);
        ohi[(size_t)jp * DD + k0 + tx] = hi;
        olo[(size_t)jp * DD + k0 + tx] = __float2bfloat16(v - __bfloat162float(hi));
    }
}

// ---------------------------------------------------------------------------
// xW GEMM via mma.sync (unchanged working version)
// ---------------------------------------------------------------------------
#define G_STAGE 65536   // Ah 16K | Al 16K | Bh 16K | Bl 16K
#define G_SMEM  (3 * G_STAGE)

__global__ __launch_bounds__(256, 1)
void xw_gemm_mma() {
    extern __shared__ char smem[];
    const uint32_t sb = smem_u32(smem);
    const int tid = threadIdx.x;
    const int nbase = blockIdx.x * 128;
    const int mbase = blockIdx.y * 128;

    const __nv_bfloat16* Ahg = g_xhi + (size_t)mbase * DD;
    const __nv_bfloat16* Alg = g_xlo + (size_t)mbase * DD;
    const __nv_bfloat16* Bhg = g_wxt_hi + (size_t)nbase * DD;
    const __nv_bfloat16* Blg = g_wxt_lo + (size_t)nbase * DD;

    auto cp_chunk = [&](int c, int st) {
        const int k0 = c * 64;
        const uint32_t ah = sb + st * G_STAGE;
        #pragma unroll
        for (int i = 0; i < 4; i++) {
            int idx = tid + i * 256;
            int row = idx >> 3, ch = idx & 7;
            uint32_t o = (uint32_t)(row * 128) + (uint32_t)((ch * 16) ^ ((row & 7) * 16));
            CP16(ah + o,         (const char*)(Ahg + (size_t)row * DD + k0) + ch * 16);
            CP16(ah + 16384 + o, (const char*)(Alg + (size_t)row * DD + k0) + ch * 16);
            CP16(ah + 32768 + o, (const char*)(Bhg + (size_t)row * DD + k0) + ch * 16);
            CP16(ah + 49152 + o, (const char*)(Blg + (size_t)row * DD + k0) + ch * 16);
        }
        CP_COMMIT();
    };

    const int wid = tid >> 5, lane = tid & 31;
    const int wm = wid >> 2, wn = wid & 3;      // warp grid 2x4
    const int m0 = wm * 64, n0 = wn * 32;
    const int gid = lane >> 2, tig = lane & 3;

    const int a_r = lane & 15;
    const uint32_t a_k = ((lane >> 4) & 1) * 16;
    const uint32_t a_x = (uint32_t)((a_r & 7) * 16);
    const int b_r = (lane & 7) + ((lane >> 4) & 1) * 8;
    const uint32_t b_k = ((lane >> 3) & 1) * 16;
    const uint32_t b_x = (uint32_t)((lane & 7) * 16);

    float acc[4][4][4];
    #pragma unroll
    for (int mt = 0; mt < 4; mt++)
        #pragma unroll
        for (int nt = 0; nt < 4; nt++)
            #pragma unroll
            for (int q = 0; q < 4; q++) acc[mt][nt][q] = 0.0f;

    cp_chunk(0, 0);
    cp_chunk(1, 1);

    for (int c = 0; c < 16; c++) {
        if (c + 2 < 16) { cp_chunk(c + 2, (c + 2) % 3); CP_WAIT(2); }
        else if (c + 1 < 16) { CP_WAIT(1); }
        else { CP_WAIT(0); }
        __syncthreads();

        const uint32_t base = sb + (c % 3) * G_STAGE;
        #pragma unroll
        for (int kk = 0; kk < 4; kk++) {
            const uint32_t ka = ((uint32_t)(kk * 32) + a_k) ^ a_x;
            const uint32_t kb = ((uint32_t)(kk * 32) + b_k) ^ b_x;
            uint32_t ah[4][4], al[4][4], bh[2][4], bl[2][4];
            #pragma unroll
            for (int mt = 0; mt < 4; mt++) {
                uint32_t ra = base + (uint32_t)((m0 + mt * 16 + a_r) * 128);
                LDSM4(ah[mt][0], ah[mt][1], ah[mt][2], ah[mt][3], ra + ka);
                LDSM4(al[mt][0], al[mt][1], al[mt][2], al[mt][3], ra + 16384 + ka);
            }
            #pragma unroll
            for (int p = 0; p < 2; p++) {
                uint32_t rb = base + 32768 + (uint32_t)((n0 + p * 16 + b_r) * 128);
                LDSM4(bh[p][0], bh[p][1], bh[p][2], bh[p][3], rb + kb);
                LDSM4(bl[p][0], bl[p][1], bl[p][2], bl[p][3], rb + 16384 + kb);
            }
            #pragma unroll
            for (int mt = 0; mt < 4; mt++)
                #pragma unroll
                for (int nt = 0; nt < 4; nt++) {
                    const int p = nt >> 1, hf = (nt & 1) * 2;
                    MMA_BF16(acc[mt][nt][0], acc[mt][nt][1], acc[mt][nt][2], acc[mt][nt][3],
                             ah[mt][0], ah[mt][1], ah[mt][2], ah[mt][3],
                             bh[p][hf], bh[p][hf + 1]);
                    MMA_BF16(acc[mt][nt][0], acc[mt][nt][1], acc[mt][nt][2], acc[mt][nt][3],
                             ah[mt][0], ah[mt][1], ah[mt][2], ah[mt][3],
                             bl[p][hf], bl[p][hf + 1]);
                    MMA_BF16(acc[mt][nt][0], acc[mt][nt][1], acc[mt][nt][2], acc[mt][nt][3],
                             al[mt][0], al[mt][1], al[mt][2], al[mt][3],
                             bh[p][hf], bh[p][hf + 1]);
                }
        }
        __syncthreads();
    }

    #pragma unroll
    for (int nt = 0; nt < 4; nt++) {
        const int col = nbase + n0 + nt * 8 + tig * 2;
        float2 bv = *(const float2*)&g_biasp[col];
        #pragma unroll
        for (int mt = 0; mt < 4; mt++) {
            const int row = mbase + m0 + mt * 16 + gid;
            float2 v0, v1;
            v0.x = acc[mt][nt][0] + bv.x; v0.y = acc[mt][nt][1] + bv.y;
            v1.x = acc[mt][nt][2] + bv.x; v1.y = acc[mt][nt][3] + bv.y;
            *(float2*)&g_xw[(size_t)row * FOURH + col] = v0;
            *(float2*)&g_xw[(size_t)(row + 8) * FOURH + col] = v1;
        }
    }
}

// ---------------------------------------------------------------------------
// Persistent LSTM recurrence: warp-autonomous mainloop (NO block syncs inside).
// 128 CTAs x 256 threads. CTA jb owns j' [jb*32, jb*32+32) (8 hidden x 4 gates).
// Warp w owns batch rows n in [w*8, w*8+8): loads its own h rows + xw rows,
// computes m32 x n8 with private cp.async pipeline, does warp-local gates.
// ---------------------------------------------------------------------------
#define PA_HI  0                 // 64KB Wh_hi slice, 16 chunks x 4KB
#define PA_LO  65536             // 64KB Wh_lo slice
#define PB     131072            // 4 stages x 16KB (h_hi 8K | h_lo 8K)
#define PXW    196608            // 8KB xw tile (64 n x 32 j')
#define PASW   204800            // 8 warps x 1152B staging
#define P_SMEM (204800 + 9216)

__global__ __launch_bounds__(256, 1)
void lstm_persistent(float* __restrict__ out) {
    extern __shared__ char smem[];
    const uint32_t sb = smem_u32(smem);
    const int tid = threadIdx.x;
    const int jb = blockIdx.x;                 // 0..127
    const int wid = tid >> 5, lane = tid & 31;
    const int n0 = wid * 8;                    // warp's batch rows
    const int gid = lane >> 2, tig = lane & 3;

    // A (Wh) ldmatrix addressing
    const int a_r = lane & 15;
    const uint32_t a_k = ((lane >> 4) & 1) * 16;
    const uint32_t a_x = (uint32_t)((a_r & 7) * 16);
    // B ldmatrix addressing (n8 x k32 via x4)
    const int b_row = lane & 7;
    const int b_mat = lane >> 3;

    // ---- load persistent Wh slice (16 k-chunks x 32 rows x 128B, hi+lo) ----
    {
        const __nv_bfloat16* Ahg = g_wht_hi + (size_t)jb * 32 * DD;
        const __nv_bfloat16* Alg = g_wht_lo + (size_t)jb * 32 * DD;
        #pragma unroll
        for (int i = 0; i < 16; i++) {
            int idx = tid + i * 256;
            int c = idx >> 8;
            int row = (idx >> 3) & 31;
            int ch = idx & 7;
            uint32_t o = (uint32_t)(c * 4096 + row * 128)
                       + (uint32_t)((ch * 16) ^ ((row & 7) * 16));
            CP16(sb + PA_HI + o, (const char*)(Ahg + (size_t)row * DD + c * 64) + ch * 16);
            CP16(sb + PA_LO + o, (const char*)(Alg + (size_t)row * DD + c * 64) + ch * 16);
        }
        CP_COMMIT();
        CP_WAIT(0);
        __syncthreads();
    }

    float creg[2] = {0.0f, 0.0f};

    for (unsigned t = 0; t < TT; t++) {
        const __nv_bfloat16* Bhg = g_h_hi[t & 1];
        const __nv_bfloat16* Blg = g_h_lo[t & 1];

        // warp-private B chunk load: 8 rows x 64 k (hi+lo), 4 cp/lane
        auto cp_b = [&](int c, int st) {
            const int k0 = c * 64;
            const uint32_t bb = sb + PB + (uint32_t)(st * 16384);
            #pragma unroll
            for (int q = 0; q < 2; q++) {
                int idx = lane + q * 32;      // 0..63
                int row = idx >> 3;           // 0..7
                int ch = idx & 7;
                uint32_t o = (uint32_t)((n0 + row) * 128) + (uint32_t)((ch * 16) ^ (row * 16));
                CP16(bb + o,        (const char*)(Bhg + (size_t)(n0 + row) * DD + k0) + ch * 16);
                CP16(bb + 8192 + o, (const char*)(Blg + (size_t)(n0 + row) * DD + k0) + ch * 16);
            }
        };

        // group 0: warp's xw rows + B chunk 0
        #pragma unroll
        for (int q = 0; q < 2; q++) {
            int idx = lane + q * 32;
            int row = idx >> 3, ch = idx & 7;
            CP16(sb + PXW + (uint32_t)((n0 + row) * 128 + ch * 16),
                 (const char*)(g_xw + ((size_t)(n0 + row) * TT + t) * FOURH + jb * 32) + ch * 16);
        }
        cp_b(0, 0); CP_COMMIT();
        cp_b(1, 1); CP_COMMIT();
        cp_b(2, 2); CP_COMMIT();

        float acc[2][4];
        #pragma unroll
        for (int mt = 0; mt < 2; mt++)
            #pragma unroll
            for (int q = 0; q < 4; q++) acc[mt][q] = 0.0f;

        for (int c = 0; c < 16; c++) {
            if (c + 3 < 16)      { cp_b(c + 3, (c + 3) & 3); CP_COMMIT(); CP_WAIT(3); }
            else if (c == 13)    { CP_WAIT(2); }
            else if (c == 14)    { CP_WAIT(1); }
            else                 { CP_WAIT(0); }
            __syncwarp();

            const uint32_t bst = sb + PB + (uint32_t)((c & 3) * 16384);
            const uint32_t ahc = sb + PA_HI + (uint32_t)(c * 4096);
            const uint32_t alc = sb + PA_LO + (uint32_t)(c * 4096);
            #pragma unroll
            for (int k2 = 0; k2 < 2; k2++) {
                uint32_t bh[4], bl[4];
                const uint32_t bo = (uint32_t)((n0 + b_row) * 128)
                                  + (uint32_t)((k2 * 64 + b_mat * 16) ^ (b_row * 16));
                LDSM4(bh[0], bh[1], bh[2], bh[3], bst + bo);
                LDSM4(bl[0], bl[1], bl[2], bl[3], bst + 8192 + bo);
                #pragma unroll
                for (int hf = 0; hf < 2; hf++) {
                    const int kk = k2 * 2 + hf;
                    const uint32_t ka = ((uint32_t)(kk * 32) + a_k) ^ a_x;
                    #pragma unroll
                    for (int mt = 0; mt < 2; mt++) {
                        uint32_t ah[4], al[4];
                        const uint32_t ao = (uint32_t)((mt * 16 + a_r) * 128) + ka;
                        LDSM4(ah[0], ah[1], ah[2], ah[3], ahc + ao);
                        LDSM4(al[0], al[1], al[2], al[3], alc + ao);
                        MMA_BF16(acc[mt][0], acc[mt][1], acc[mt][2], acc[mt][3],
                                 ah[0], ah[1], ah[2], ah[3], bh[hf * 2], bh[hf * 2 + 1]);
                        MMA_BF16(acc[mt][0], acc[mt][1], acc[mt][2], acc[mt][3],
                                 ah[0], ah[1], ah[2], ah[3], bl[hf * 2], bl[hf * 2 + 1]);
                        MMA_BF16(acc[mt][0], acc[mt][1], acc[mt][2], acc[mt][3],
                                 al[0], al[1], al[2], al[3], bh[hf * 2], bh[hf * 2 + 1]);
                    }
                }
            }
        }

        // warp-local epilogue: stage acc -> asw[n_local][j'] (stride 36), gates
        float* asw = (float*)(smem + PASW + wid * 1152);
        #pragma unroll
        for (int mt = 0; mt < 2; mt++) {
            asw[(tig * 2 + 0) * 36 + mt * 16 + gid]     = acc[mt][0];
            asw[(tig * 2 + 1) * 36 + mt * 16 + gid]     = acc[mt][1];
            asw[(tig * 2 + 0) * 36 + mt * 16 + gid + 8] = acc[mt][2];
            asw[(tig * 2 + 1) * 36 + mt * 16 + gid + 8] = acc[mt][3];
        }
        __syncwarp();

        {
            const float* xws = (const float*)(smem + PXW);
            __nv_bfloat16* nhhi = g_h_hi[(t + 1) & 1];
            __nv_bfloat16* nhlo = g_h_lo[(t + 1) & 1];
            #pragma unroll
            for (int i = 0; i < 2; i++) {
                const int p = lane + i * 32;    // 0..63
                const int nl = p >> 3;          // 0..7
                const int jhl = p & 7;          // 0..7
                const float* ar = asw + nl * 36 + jhl * 4;
                const float* xr = xws + (n0 + nl) * 32 + jhl * 4;
                float ig = fsigmoid(ar[0] + xr[0]);
                float fg = fsigmoid(ar[1] + xr[1]);
                float og = fsigmoid(ar[2] + xr[2]);
                float gg = ftanh(ar[3] + xr[3]);
                float cn = fg * creg[i] + ig * gg;
                creg[i] = cn;
                float h = og * ftanh(cn);
                const int n = n0 + nl;
                const int jg = jb * 8 + jhl;
                out[((size_t)n * TT + t) * HH + jg] = h;
                __nv_bfloat16 hh = __float2bfloat16(h);
                const int hidx = n * HH + jg;
                nhhi[hidx] = hh;
                nhlo[hidx] = __float2bfloat16(h - __bfloat162float(hh));
            }
        }

        // global barrier (128 CTAs, all resident)
        __syncthreads();
        if (tid == 0) {
            __threadfence();
            atomicAdd(&g_bar, 1u);
            const unsigned target = (t + 1u) * (unsigned)P_CTAS;
            while (*(volatile unsigned*)&g_bar < target) { }
            __threadfence();
        }
        __syncthreads();
    }
}

// ---------------------------------------------------------------------------
extern "C" void kernel_launch(void* const* d_in, const int* in_sizes, int n_in,
                              void* d_out, int out_size)
{
    const float* x  = (const float*)d_in[0];   // (64, 512, 1024)
    const float* h0 = (const float*)d_in[1];   // (64, 1024)
    const float* Wx = (const float*)d_in[2];   // (1024, 4096)
    const float* Wh = (const float*)d_in[3];   // (1024, 4096)
    const float* b  = (const float*)d_in[4];   // (4096,)
    float* out = (float*)d_out;                // (64, 512, 1024)

    cudaFuncSetAttribute(xw_gemm_mma,     cudaFuncAttributeMaxDynamicSharedMemorySize, G_SMEM);
    cudaFuncSetAttribute(lstm_persistent, cudaFuncAttributeMaxDynamicSharedMemorySize, P_SMEM);

    __nv_bfloat16 *wxt_hi, *wxt_lo, *wht_hi, *wht_lo;
    cudaGetSymbolAddress((void**)&wxt_hi, g_wxt_hi);
    cudaGetSymbolAddress((void**)&wxt_lo, g_wxt_lo);
    cudaGetSymbolAddress((void**)&wht_hi, g_wht_hi);
    cudaGetSymbolAddress((void**)&wht_lo, g_wht_lo);

    prep_small_kernel<<<64, 1024>>>(h0, b);
    split_x_kernel<<<(NB * TT * DD / 4) / 256, 256>>>(x);
    transpose_split_kernel<<<dim3(DD / 32, FOURH / 32), dim3(32, 8)>>>(Wx, wxt_hi, wxt_lo);
    transpose_split_kernel<<<dim3(DD / 32, FOURH / 32), dim3(32, 8)>>>(Wh, wht_hi, wht_lo);

    xw_gemm_mma<<<dim3(32, 256), 256, G_SMEM>>>();

    lstm_persistent<<<P_CTAS, 256, P_SMEM>>>(out);
}